// round 13
// baseline (speedup 1.0000x reference)
#include <cuda_runtime.h>
#include <cuda_fp16.h>
#include <math.h>
#include <stdint.h>

// Problem dims
#define L_   12
#define D_   1024
#define NH_  16
#define HD_  64
#define HID_ 2816
#define V_   50257
#define B_   8
#define T_   1024
#define M_   (B_*T_)        // 8192 tokens

// ---------------------------------------------------------------------------
// Scratch (static device globals — no allocations allowed)
// ---------------------------------------------------------------------------
__device__ float g_x  [M_ * D_];
__device__ float g_xf [B_ * D_];

__device__ __half g_ah[M_ * D_];
__device__ __half g_al[M_ * D_];
__device__ __half g_uh[M_ * HID_];
__device__ __half g_ul[M_ * HID_];

__device__ __half g_qh[M_ * D_];
__device__ __half g_ql[M_ * D_];
__device__ __half g_kh[M_ * D_];
__device__ __half g_kl[M_ * D_];
__device__ __half g_vh[M_ * D_];
__device__ __half g_vl[M_ * D_];

__device__ __half g_wch[L_ * 3 * D_ * D_];
__device__ __half g_wcl[L_ * 3 * D_ * D_];
__device__ __half g_wph[L_ * D_ * D_];
__device__ __half g_wpl[L_ * D_ * D_];
__device__ __half g_w1h[L_ * HID_ * D_];
__device__ __half g_w1l[L_ * HID_ * D_];
__device__ __half g_w3h[L_ * HID_ * D_];
__device__ __half g_w3l[L_ * HID_ * D_];
__device__ __half g_w2h[L_ * D_ * HID_];
__device__ __half g_w2l[L_ * D_ * HID_];

// ---------------------------------------------------------------------------
// Helpers
// ---------------------------------------------------------------------------
__device__ __forceinline__ uint32_t smem_u32(const void* p) {
    uint32_t a;
    asm("{ .reg .u64 t; cvta.to.shared.u64 t, %1; cvt.u32.u64 %0, t; }"
        : "=r"(a) : "l"(p));
    return a;
}

__device__ __forceinline__ uint32_t packh(float x, float y) {
    uint32_t r;
    asm("cvt.rn.f16x2.f32 %0, %1, %2;" : "=r"(r) : "f"(y), "f"(x));
    return r;
}

__device__ __forceinline__ float hf(float x) {
    return __half2float(__float2half_rn(x));
}

__device__ __forceinline__ void ldm_x4(uint32_t* r, uint32_t addr) {
    asm volatile("ldmatrix.sync.aligned.m8n8.x4.shared.b16 {%0,%1,%2,%3}, [%4];"
                 : "=r"(r[0]), "=r"(r[1]), "=r"(r[2]), "=r"(r[3]) : "r"(addr));
}
__device__ __forceinline__ void ldm_x4_t(uint32_t* r, uint32_t addr) {
    asm volatile("ldmatrix.sync.aligned.m8n8.x4.trans.shared.b16 {%0,%1,%2,%3}, [%4];"
                 : "=r"(r[0]), "=r"(r[1]), "=r"(r[2]), "=r"(r[3]) : "r"(addr));
}

__device__ __forceinline__ void mma16816(float* c, const uint32_t* a,
                                         const uint32_t* b) {
    asm volatile(
        "mma.sync.aligned.m16n8k16.row.col.f32.f16.f16.f32 "
        "{%0,%1,%2,%3}, {%4,%5,%6,%7}, {%8,%9}, {%0,%1,%2,%3};"
        : "+f"(c[0]), "+f"(c[1]), "+f"(c[2]), "+f"(c[3])
        : "r"(a[0]), "r"(a[1]), "r"(a[2]), "r"(a[3]), "r"(b[0]), "r"(b[1]));
}

__device__ __forceinline__ void cvt8(float4 f0, float4 f1, uint4& hi, uint4& lo) {
    float h0 = hf(f0.x), h1 = hf(f0.y), h2 = hf(f0.z), h3 = hf(f0.w);
    float h4 = hf(f1.x), h5 = hf(f1.y), h6 = hf(f1.z), h7 = hf(f1.w);
    hi.x = packh(h0, h1); hi.y = packh(h2, h3);
    hi.z = packh(h4, h5); hi.w = packh(h6, h7);
    lo.x = packh(f0.x - h0, f0.y - h1);
    lo.y = packh(f0.z - h2, f0.w - h3);
    lo.z = packh(f1.x - h4, f1.y - h5);
    lo.w = packh(f1.z - h6, f1.w - h7);
}

__device__ __forceinline__ void cpa16(uint32_t d, const void* s) {
    asm volatile("cp.async.cg.shared.global [%0], [%1], 16;" :: "r"(d), "l"(s));
}
__device__ __forceinline__ void cpcommit() {
    asm volatile("cp.async.commit_group;");
}
template <int N>
__device__ __forceinline__ void cpwait() {
    asm volatile("cp.async.wait_group %0;" :: "n"(N));
}

// ---------------------------------------------------------------------------
// Fused weight converter
// ---------------------------------------------------------------------------
#define WN0 4718592L
#define WN1 1572864L
#define WN2 4325376L
#define WTOT (WN0 + WN1 + 3 * WN2)

__global__ void wcvt_all_k(const float* __restrict__ cw, const float* __restrict__ pw,
                           const float* __restrict__ w1, const float* __restrict__ w3,
                           const float* __restrict__ w2,
                           __half* cwh, __half* cwl, __half* pwh, __half* pwl,
                           __half* w1h, __half* w1l, __half* w3h, __half* w3l,
                           __half* w2h, __half* w2l) {
    long i = (long)blockIdx.x * 256 + threadIdx.x;
    const float* src; __half* hi; __half* lo;
    if (i < WN0)              { src = cw; hi = cwh; lo = cwl; }
    else if ((i -= WN0) < WN1){ src = pw; hi = pwh; lo = pwl; }
    else if ((i -= WN1) < WN2){ src = w1; hi = w1h; lo = w1l; }
    else if ((i -= WN2) < WN2){ src = w3; hi = w3h; lo = w3l; }
    else { i -= WN2;            src = w2; hi = w2h; lo = w2l; }
    float4 f0 = ((const float4*)src)[i * 2];
    float4 f1 = ((const float4*)src)[i * 2 + 1];
    uint4 h, l;
    cvt8(f0, f1, h, l);
    ((uint4*)hi)[i] = h;
    ((uint4*)lo)[i] = l;
}

// ---------------------------------------------------------------------------
// GEMM mainloop — R13: 128x128 CTA tile, FOUR warps of 64x64 warp tiles
// (128 threads). Halves LDSM fragment traffic per MMA -> smem crossbar no
// longer binds (104KB vs 136KB per chunk). One barrier per chunk, A ping-pong.
// Per-accumulator order unchanged (hh, lh, hl) -> bit-identical results.
// ---------------------------------------------------------------------------
#define RSTRIDE 80
#define STAGE_BYTES 40960
#define OFF_ALO 10240
#define OFF_WHI 20480
#define OFF_WLO 30720

struct LoaderPtrs {
    const __half *paR, *palR;   // A row tid
    const __half *pwR, *pwlR;   // B row tid
};

__device__ __forceinline__ void gemm_mainloop(
    uint32_t sb, int tid, int K, const LoaderPtrs& P,
    const uint32_t* arow, const uint32_t* brow, float acc[4][8][4]) {

    auto load_stage = [&](int s, int kc) {
        uint32_t base = sb + (uint32_t)s * STAGE_BYTES;
        uint32_t d = base + (uint32_t)(tid * RSTRIDE);
        #pragma unroll
        for (int c = 0; c < 4; c++) {
            cpa16(d + c * 16,           P.paR  + kc + c * 8);
            cpa16(d + OFF_ALO + c * 16, P.palR + kc + c * 8);
            cpa16(d + OFF_WHI + c * 16, P.pwR  + kc + c * 8);
            cpa16(d + OFF_WLO + c * 16, P.pwlR + kc + c * 8);
        }
    };

    const int nc = K >> 5;
    load_stage(0, 0);
    cpcommit();

    for (int j = 0; j < nc; j++) {
        cpwait<0>();
        __syncthreads();
        if (j + 1 < nc) {
            load_stage((j + 1) & 1, (j + 1) << 5);
            cpcommit();
        }

        const uint32_t base = sb + (uint32_t)(j & 1) * STAGE_BYTES;
        #pragma unroll
        for (int ks = 0; ks < 2; ks++) {
            const uint32_t ko = (uint32_t)(ks * 32);
            // B fragments: 64 cols, hi+lo (8 LDSM)
            uint32_t bh[8][2], bl[8][2];
            #pragma unroll
            for (int np = 0; np < 4; np++) {
                uint32_t t4[4];
                ldm_x4(t4, base + OFF_WHI + brow[np] + ko);
                bh[2*np][0] = t4[0]; bh[2*np][1] = t4[1];
                bh[2*np+1][0] = t4[2]; bh[2*np+1][1] = t4[3];
                ldm_x4(t4, base + OFF_WLO + brow[np] + ko);
                bl[2*np][0] = t4[0]; bl[2*np][1] = t4[1];
                bl[2*np+1][0] = t4[2]; bl[2*np+1][1] = t4[3];
            }
            // A fragments ping-pong over mt
            uint32_t ahb[2][4], alb[2][4];
            ldm_x4(ahb[0], base +           arow[0] + ko);
            ldm_x4(alb[0], base + OFF_ALO + arow[0] + ko);
            #pragma unroll
            for (int mt = 0; mt < 4; mt++) {
                const int cur = mt & 1;
                if (mt < 3) {
                    ldm_x4(ahb[cur ^ 1], base +           arow[mt + 1] + ko);
                    ldm_x4(alb[cur ^ 1], base + OFF_ALO + arow[mt + 1] + ko);
                }
                #pragma unroll
                for (int nt = 0; nt < 8; nt++)
                    mma16816(acc[mt][nt], ahb[cur], bh[nt]);
                #pragma unroll
                for (int nt = 0; nt < 8; nt++)
                    mma16816(acc[mt][nt], alb[cur], bh[nt]);
                #pragma unroll
                for (int nt = 0; nt < 8; nt++)
                    mma16816(acc[mt][nt], ahb[cur], bl[nt]);
            }
        }
    }
    __syncthreads();
}

#define GEMM_PROLOG                                                            \
    extern __shared__ __align__(16) char sm[];                                 \
    const uint32_t sb = smem_u32(sm);                                          \
    const int tid = threadIdx.x;                                               \
    const int warp = tid >> 5, lane = tid & 31;                                \
    const int wm = warp & 1, wn = warp >> 1;                                   \
    const int gid = lane >> 2, tg = lane & 3;                                  \
    const int l15 = lane & 15, l16 = (lane >> 4) & 1;                          \
    const int l7 = lane & 7, l8 = (lane >> 3) & 1;                             \
    uint32_t arow[4], brow[4];                                                 \
    _Pragma("unroll")                                                          \
    for (int mt = 0; mt < 4; mt++)                                             \
        arow[mt] = (uint32_t)((wm * 64 + mt * 16 + l15) * RSTRIDE + l16 * 16); \
    _Pragma("unroll")                                                          \
    for (int p = 0; p < 4; p++)                                                \
        brow[p] = (uint32_t)((wn * 64 + p * 16 + l7 + l16 * 8) * RSTRIDE + l8 * 16); \
    float acc[4][8][4];                                                        \
    _Pragma("unroll")                                                          \
    for (int i = 0; i < 4; i++)                                                \
        _Pragma("unroll")                                                      \
        for (int j = 0; j < 8; j++)                                            \
            _Pragma("unroll")                                                  \
            for (int c = 0; c < 4; c++) acc[i][j][c] = 0.f;

// ---------------------------------------------------------------------------
// Standard GEMM "NT" (proj / w2): C = A@W^T (+bias)(+residual)
// ---------------------------------------------------------------------------
__global__ void __launch_bounds__(128, 2)
hgemm16(const __half* __restrict__ a_hi, const __half* __restrict__ a_lo,
        const __half* __restrict__ w_hi, const __half* __restrict__ w_lo,
        const float* __restrict__ bias, float* __restrict__ C,
        int M, int N, int K, int residual) {
    GEMM_PROLOG
    const int by = blockIdx.y * 128, bx = blockIdx.x * 128;
    LoaderPtrs P;
    P.paR  = a_hi + (size_t)(by + tid) * K;
    P.palR = a_lo + (size_t)(by + tid) * K;
    P.pwR  = w_hi + (size_t)(bx + tid) * K;
    P.pwlR = w_lo + (size_t)(bx + tid) * K;
    gemm_mainloop(sb, tid, K, P, arow, brow, acc);

    const size_t mBase = (size_t)by + wm * 64;
    const int    nBase = bx + wn * 64;
    #pragma unroll
    for (int mt = 0; mt < 4; mt++) {
        #pragma unroll
        for (int nt = 0; nt < 8; nt++) {
            int c0 = nBase + nt * 8 + tg * 2;
            float b0 = bias ? bias[c0]     : 0.f;
            float b1 = bias ? bias[c0 + 1] : 0.f;
            size_t r0 = mBase + mt * 16 + gid;
            float* p0 = C + r0 * N + c0;
            float* p1 = C + (r0 + 8) * N + c0;
            float v00 = acc[mt][nt][0] + b0, v01 = acc[mt][nt][1] + b1;
            float v10 = acc[mt][nt][2] + b0, v11 = acc[mt][nt][3] + b1;
            if (residual) { v00 += p0[0]; v01 += p0[1]; v10 += p1[0]; v11 += p1[1]; }
            p0[0] = v00; p0[1] = v01;
            p1[0] = v10; p1[1] = v11;
        }
    }
}

// ---------------------------------------------------------------------------
// QKV GEMM with fused bias + RoPE + fp16 hi/lo split output.
// Grid (3*D/128 = 24, M/128). Region by blockIdx.x: 0..7 q, 8..15 k, 16..23 v.
// ---------------------------------------------------------------------------
__global__ void __launch_bounds__(128, 2)
hgemm16_qkv(const __half* __restrict__ a_hi, const __half* __restrict__ a_lo,
            const __half* __restrict__ w_hi, const __half* __restrict__ w_lo,
            const float* __restrict__ bias,
            __half* __restrict__ qh, __half* __restrict__ ql,
            __half* __restrict__ kh, __half* __restrict__ kl,
            __half* __restrict__ vh, __half* __restrict__ vl) {
    GEMM_PROLOG
    const int K = D_;
    const int by = blockIdx.y * 128, bx = blockIdx.x * 128;
    LoaderPtrs P;
    P.paR  = a_hi + (size_t)(by + tid) * K;
    P.palR = a_lo + (size_t)(by + tid) * K;
    P.pwR  = w_hi + (size_t)(bx + tid) * K;
    P.pwlR = w_lo + (size_t)(bx + tid) * K;
    gemm_mainloop(sb, tid, K, P, arow, brow, acc);

    // stage fp32 tile (+bias) in smem: [128][132]
    float* smf = (float*)sm;
    #pragma unroll
    for (int mt = 0; mt < 4; mt++) {
        #pragma unroll
        for (int nt = 0; nt < 8; nt++) {
            int col = wn * 64 + nt * 8 + tg * 2;
            int row = wm * 64 + mt * 16 + gid;
            float b0 = bias[bx + col], b1 = bias[bx + col + 1];
            smf[row * 132 + col]           = acc[mt][nt][0] + b0;
            smf[row * 132 + col + 1]       = acc[mt][nt][1] + b1;
            smf[(row + 8) * 132 + col]     = acc[mt][nt][2] + b0;
            smf[(row + 8) * 132 + col + 1] = acc[mt][nt][3] + b1;
        }
    }
    __syncthreads();

    const int region = blockIdx.x >> 3;      // 0 q, 1 k, 2 v
    #pragma unroll 4
    for (int it = 0; it < 32; it++) {
        int idx = tid + it * 128;            // 4096 quads
        int r = idx >> 5;
        int c4 = (idx & 31) * 4;
        int mrow = by + r;
        float4 x4 = *(float4*)&smf[r * 132 + c4];
        float o0, o1, o2, o3;
        __half *dh, *dl;
        int dcol;
        if (region < 2) {
            int cg = bx + c4;
            int hc = cg & 63;
            int hi_half = hc & 32;
            float4 p4 = *(float4*)&smf[r * 132 + (hi_half ? c4 - 32 : c4 + 32)];
            int t = mrow & (T_ - 1);
            float oo[4];
            float xv[4] = {x4.x, x4.y, x4.z, x4.w};
            float pv[4] = {p4.x, p4.y, p4.z, p4.w};
            #pragma unroll
            for (int e = 0; e < 4; e++) {
                int i = (hc & 31) + e;
                float inv = exp2f((float)i * (-13.28771237954945f / 32.0f));
                float ang = (float)t * inv;
                float sn, cs;
                sincosf(ang, &sn, &cs);
                oo[e] = hi_half ? (xv[e] * cs + pv[e] * sn)
                                : (xv[e] * cs - pv[e] * sn);
            }
            if (region == 0) {
                o0 = oo[0] * 0.125f; o1 = oo[1] * 0.125f;
                o2 = oo[2] * 0.125f; o3 = oo[3] * 0.125f;
                dh = qh; dl = ql; dcol = cg;
            } else {
                o0 = oo[0]; o1 = oo[1]; o2 = oo[2]; o3 = oo[3];
                dh = kh; dl = kl; dcol = cg - D_;
            }
        } else {
            o0 = x4.x; o1 = x4.y; o2 = x4.z; o3 = x4.w;
            dh = vh; dl = vl; dcol = bx + c4 - 2 * D_;
        }
        float h0 = hf(o0), h1 = hf(o1), h2 = hf(o2), h3 = hf(o3);
        uint2 hh, ll;
        hh.x = packh(h0, h1); hh.y = packh(h2, h3);
        ll.x = packh(o0 - h0, o1 - h1); ll.y = packh(o2 - h2, o3 - h3);
        *(uint2*)(dh + (size_t)mrow * D_ + dcol) = hh;
        *(uint2*)(dl + (size_t)mrow * D_ + dcol) = ll;
    }
}

// ---------------------------------------------------------------------------
// Fused GLU GEMM: B rows 0..63 = w1[n0..n0+63], rows 64..127 = w3[n0..n0+63].
// out = silu(u)*g as fp16 hi/lo. Grid (HID/64 = 44, M/128).
// ---------------------------------------------------------------------------
__global__ void __launch_bounds__(128, 2)
hgemm16_glu(const __half* __restrict__ a_hi, const __half* __restrict__ a_lo,
            const __half* __restrict__ w1h, const __half* __restrict__ w1l,
            const __half* __restrict__ w3h, const __half* __restrict__ w3l,
            __half* __restrict__ oh, __half* __restrict__ ol) {
    GEMM_PROLOG
    const int K = D_;
    const int by = blockIdx.y * 128;
    const int bx64 = blockIdx.x * 64;
    LoaderPtrs P;
    P.paR  = a_hi + (size_t)(by + tid) * K;
    P.palR = a_lo + (size_t)(by + tid) * K;
    if (tid < 64) {
        P.pwR  = w1h + (size_t)(bx64 + tid) * K;
        P.pwlR = w1l + (size_t)(bx64 + tid) * K;
    } else {
        P.pwR  = w3h + (size_t)(bx64 + tid - 64) * K;
        P.pwlR = w3l + (size_t)(bx64 + tid - 64) * K;
    }
    gemm_mainloop(sb, tid, K, P, arow, brow, acc);

    // stage fp32 [128][132]: cols 0..63 = u, 64..127 = g
    float* smf = (float*)sm;
    #pragma unroll
    for (int mt = 0; mt < 4; mt++) {
        #pragma unroll
        for (int nt = 0; nt < 8; nt++) {
            int col = wn * 64 + nt * 8 + tg * 2;
            int row = wm * 64 + mt * 16 + gid;
            smf[row * 132 + col]           = acc[mt][nt][0];
            smf[row * 132 + col + 1]       = acc[mt][nt][1];
            smf[(row + 8) * 132 + col]     = acc[mt][nt][2];
            smf[(row + 8) * 132 + col + 1] = acc[mt][nt][3];
        }
    }
    __syncthreads();

    #pragma unroll 4
    for (int it = 0; it < 16; it++) {
        int idx = tid + it * 128;            // 2048 quads (128 x 64 / 4)
        int r = idx >> 4;
        int c4 = (idx & 15) * 4;
        float4 uv = *(float4*)&smf[r * 132 + c4];
        float4 gv = *(float4*)&smf[r * 132 + c4 + 64];
        float o0 = uv.x / (1.f + expf(-uv.x)) * gv.x;
        float o1 = uv.y / (1.f + expf(-uv.y)) * gv.y;
        float o2 = uv.z / (1.f + expf(-uv.z)) * gv.z;
        float o3 = uv.w / (1.f + expf(-uv.w)) * gv.w;
        float h0 = hf(o0), h1 = hf(o1), h2 = hf(o2), h3 = hf(o3);
        uint2 hh, ll;
        hh.x = packh(h0, h1); hh.y = packh(h2, h3);
        ll.x = packh(o0 - h0, o1 - h1); ll.y = packh(o2 - h2, o3 - h3);
        size_t off = (size_t)(by + r) * HID_ + bx64 + c4;
        *(uint2*)(oh + off) = hh;
        *(uint2*)(ol + off) = ll;
    }
}

// ---------------------------------------------------------------------------
// Embedding gather
// ---------------------------------------------------------------------------
__global__ void embed_k(const int* __restrict__ tok, const float* __restrict__ wte,
                        float* __restrict__ x) {
    int m = blockIdx.x;
    int t = tok[m];
    const float4* src = (const float4*)(wte + (size_t)t * D_);
    float4* dst = (float4*)(x + (size_t)m * D_);
    dst[threadIdx.x] = src[threadIdx.x];
}

// ---------------------------------------------------------------------------
// LayerNorm cores
// ---------------------------------------------------------------------------
__device__ __forceinline__ void ln_core(const float* xr, int tid,
                                        float4& v, float& mean, float& rstd) {
    v = ((const float4*)xr)[tid];
    float s = v.x + v.y + v.z + v.w;
    float q = v.x*v.x + v.y*v.y + v.z*v.z + v.w*v.w;
    #pragma unroll
    for (int off = 16; off > 0; off >>= 1) {
        s += __shfl_down_sync(0xffffffffu, s, off);
        q += __shfl_down_sync(0xffffffffu, q, off);
    }
    __shared__ float ss[8], sq[8];
    int wi = tid >> 5, ln = tid & 31;
    if (ln == 0) { ss[wi] = s; sq[wi] = q; }
    __syncthreads();
    if (tid == 0) {
        float a = 0.f, c = 0.f;
        #pragma unroll
        for (int i = 0; i < 8; i++) { a += ss[i]; c += sq[i]; }
        ss[0] = a; sq[0] = c;
    }
    __syncthreads();
    mean = ss[0] * (1.f / D_);
    float var = sq[0] * (1.f / D_) - mean * mean;
    rstd = rsqrtf(var + 1e-5f);
}

__global__ void ln_k(const float* __restrict__ x, const float* __restrict__ w,
                     const float* __restrict__ b, float* __restrict__ o,
                     int rowStride) {
    int row = blockIdx.x, tid = threadIdx.x;
    float4 v; float mean, rstd;
    ln_core(x + (size_t)row * rowStride, tid, v, mean, rstd);
    float4 wv = ((const float4*)w)[tid];
    float4 bv = ((const float4*)b)[tid];
    float4 ov;
    ov.x = (v.x - mean) * rstd * wv.x + bv.x;
    ov.y = (v.y - mean) * rstd * wv.y + bv.y;
    ov.z = (v.z - mean) * rstd * wv.z + bv.z;
    ov.w = (v.w - mean) * rstd * wv.w + bv.w;
    ((float4*)(o + (size_t)row * D_))[tid] = ov;
}

__global__ void ln_cvt_k(const float* __restrict__ x, const float* __restrict__ w,
                         const float* __restrict__ b, __half* __restrict__ hi,
                         __half* __restrict__ lo) {
    int row = blockIdx.x, tid = threadIdx.x;
    float4 v; float mean, rstd;
    ln_core(x + (size_t)row * D_, tid, v, mean, rstd);
    float4 wv = ((const float4*)w)[tid];
    float4 bv = ((const float4*)b)[tid];
    float o0 = (v.x - mean) * rstd * wv.x + bv.x;
    float o1 = (v.y - mean) * rstd * wv.y + bv.y;
    float o2 = (v.z - mean) * rstd * wv.z + bv.z;
    float o3 = (v.w - mean) * rstd * wv.w + bv.w;
    size_t ob = (size_t)row * D_ + tid * 4;
    float h0 = hf(o0), h1 = hf(o1), h2 = hf(o2), h3 = hf(o3);
    uint2 hh, ll;
    hh.x = packh(h0, h1); hh.y = packh(h2, h3);
    ll.x = packh(o0 - h0, o1 - h1); ll.y = packh(o2 - h2, o3 - h3);
    *(uint2*)(hi + ob) = hh;
    *(uint2*)(lo + ob) = ll;
}

// ---------------------------------------------------------------------------
// MMA flash attention (proven R7 kernel, unchanged)
// ---------------------------------------------------------------------------
#define ARS 72
#define ATT_SMEM 92160

__global__ void __launch_bounds__(128)
mma_attn(const __half* __restrict__ qh, const __half* __restrict__ ql,
         const __half* __restrict__ kh, const __half* __restrict__ kl,
         const __half* __restrict__ vh, const __half* __restrict__ vl,
         __half* __restrict__ oh, __half* __restrict__ ol) {
    extern __shared__ __align__(16) __half sa[];
    const int qt = blockIdx.x, h = blockIdx.y, b = blockIdx.z;
    const int q0 = qt * 64;
    const int tid = threadIdx.x, w = tid >> 5, lane = tid & 31;
    const int gid = lane >> 2, tg = lane & 3;
    const int l7 = lane & 7, l8 = (lane >> 3) & 1, l16 = (lane >> 4) & 1;
    const uint32_t sb = smem_u32(sa);

    const int QHI = 0, QLO = 4608, STG = 9216, STGSZ = 18432;

    for (int i = tid; i < 1024; i += 128) {
        int arr = i >> 9, rem = i & 511, row = rem >> 3, ch = rem & 7;
        const __half* src = (arr ? ql : qh) +
            (size_t)(b * T_ + q0 + row) * D_ + h * 64 + ch * 8;
        *(uint4*)(sa + (arr ? QLO : QHI) + row * ARS + ch * 8) = *(const uint4*)src;
    }

    auto load_kv = [&](int s, int kt) {
        const __half* srcs[4] = {kh, kl, vh, vl};
        int base0 = STG + s * STGSZ;
        for (int i = tid; i < 2048; i += 128) {
            int arr = i >> 9, rem = i & 511, row = rem >> 3, ch = rem & 7;
            const __half* src = srcs[arr] +
                (size_t)(b * T_ + kt * 64 + row) * D_ + h * 64 + ch * 8;
            uint32_t dst = sb + (uint32_t)(base0 + arr * 4608 + row * ARS + ch * 8) * 2;
            cpa16(dst, src);
        }
    };

    load_kv(0, 0);
    cpcommit();
    __syncthreads();

    uint32_t aqh[4][4], aql[4][4];
    {
        uint32_t abase = sb + (uint32_t)((w * 16 + (lane & 15)) * ARS + l16 * 8) * 2;
        #pragma unroll
        for (int kc = 0; kc < 4; kc++) {
            ldm_x4(aqh[kc], abase + kc * 32);
            ldm_x4(aql[kc], abase + 9216 + kc * 32);
        }
    }

    float m0 = -1e30f, m1 = -1e30f, l0 = 0.f, l1 = 0.f;
    float O[8][4];
    #pragma unroll
    for (int n = 0; n < 8; n++)
        #pragma unroll
        for (int c = 0; c < 4; c++) O[n][c] = 0.f;

    const int nt = qt + 1;
    for (int kt = 0; kt < nt; kt++) {
        const int s = kt & 1;
        if (kt + 1 < nt) { load_kv(s ^ 1, kt + 1); cpcommit(); cpwait<1>(); }
        else             { cpwait<0>(); }
        __syncthreads();

        const uint32_t kbase = sb + (uint32_t)(STG + s * STGSZ) * 2;

        float S[8][4];
        #pragma unroll
        for (int n = 0; n < 8; n++)
            #pragma unroll
            for (int c = 0; c < 4; c++) S[n][c] = 0.f;

        #pragma unroll
        for (int kc = 0; kc < 4; kc++) {
            #pragma unroll
            for (int np = 0; np < 4; np++) {
                uint32_t addr = kbase +
                    (uint32_t)((np * 16 + l7 + l16 * 8) * ARS) * 2 + l8 * 16 + kc * 32;
                uint32_t bh4[4], bl4[4];
                ldm_x4(bh4, addr);
                ldm_x4(bl4, addr + 9216);
                mma16816(S[2*np],   aqh[kc], bh4 + 0);
                mma16816(S[2*np],   aql[kc], bh4 + 0);
                mma16816(S[2*np],   aqh[kc], bl4 + 0);
                mma16816(S[2*np+1], aqh[kc], bh4 + 2);
                mma16816(S[2*np+1], aql[kc], bh4 + 2);
                mma16816(S[2*np+1], aqh[kc], bl4 + 2);
            }
        }

        if (kt == qt) {
            #pragma unroll
            for (int n = 0; n < 8; n++)
                #pragma unroll
                for (int c = 0; c < 4; c++) {
                    int qg = w * 16 + gid + (c >> 1) * 8;
                    int kg = n * 8 + 2 * tg + (c & 1);
                    if (kg > qg) S[n][c] = -1e30f;
                }
        }

        float mt0 = -1e30f, mt1 = -1e30f;
        #pragma unroll
        for (int n = 0; n < 8; n++) {
            mt0 = fmaxf(mt0, fmaxf(S[n][0], S[n][1]));
            mt1 = fmaxf(mt1, fmaxf(S[n][2], S[n][3]));
        }
        mt0 = fmaxf(mt0, __shfl_xor_sync(0xffffffffu, mt0, 1));
        mt0 = fmaxf(mt0, __shfl_xor_sync(0xffffffffu, mt0, 2));
        mt1 = fmaxf(mt1, __shfl_xor_sync(0xffffffffu, mt1, 1));
        mt1 = fmaxf(mt1, __shfl_xor_sync(0xffffffffu, mt1, 2));
        float mn0 = fmaxf(m0, mt0), mn1 = fmaxf(m1, mt1);
        float a0 = expf(m0 - mn0), a1 = expf(m1 - mn1);
        float ps0 = 0.f, ps1 = 0.f;
        #pragma unroll
        for (int n = 0; n < 8; n++) {
            S[n][0] = expf(S[n][0] - mn0); ps0 += S[n][0];
            S[n][1] = expf(S[n][1] - mn0); ps0 += S[n][1];
            S[n][2] = expf(S[n][2] - mn1); ps1 += S[n][2];
            S[n][3] = expf(S[n][3] - mn1); ps1 += S[n][3];
        }
        ps0 += __shfl_xor_sync(0xffffffffu, ps0, 1);
        ps0 += __shfl_xor_sync(0xffffffffu, ps0, 2);
        ps1 += __shfl_xor_sync(0xffffffffu, ps1, 1);
        ps1 += __shfl_xor_sync(0xffffffffu, ps1, 2);
        l0 = l0 * a0 + ps0; l1 = l1 * a1 + ps1;
        m0 = mn0; m1 = mn1;
        #pragma unroll
        for (int n = 0; n < 8; n++) {
            O[n][0] *= a0; O[n][1] *= a0;
            O[n][2] *= a1; O[n][3] *= a1;
        }

        const uint32_t vbase = kbase + 18432;
        #pragma unroll
        for (int kc = 0; kc < 4; kc++) {
            float p0 = S[2*kc][0],   p1 = S[2*kc][1];
            float p2 = S[2*kc][2],   p3 = S[2*kc][3];
            float r0 = S[2*kc+1][0], r1 = S[2*kc+1][1];
            float r2 = S[2*kc+1][2], r3 = S[2*kc+1][3];
            float hp0 = hf(p0), hp1 = hf(p1), hp2 = hf(p2), hp3 = hf(p3);
            float hr0 = hf(r0), hr1 = hf(r1), hr2 = hf(r2), hr3 = hf(r3);
            uint32_t pah[4], pal[4];
            pah[0] = packh(hp0, hp1); pah[1] = packh(hp2, hp3);
            pah[2] = packh(hr0, hr1); pah[3] = packh(hr2, hr3);
            pal[0] = packh(p0 - hp0, p1 - hp1); pal[1] = packh(p2 - hp2, p3 - hp3);
            pal[2] = packh(r0 - hr0, r1 - hr1); pal[3] = packh(r2 - hr2, r3 - hr3);
            #pragma unroll
            for (int ndp = 0; ndp < 4; ndp++) {
                uint32_t addr = vbase +
                    (uint32_t)((kc * 16 + l7 + l8 * 8) * ARS) * 2 + ndp * 32 + l16 * 16;
                uint32_t bh4[4], bl4[4];
                ldm_x4_t(bh4, addr);
                ldm_x4_t(bl4, addr + 9216);
                mma16816(O[2*ndp],   pah, bh4 + 0);
                mma16816(O[2*ndp],   pal, bh4 + 0);
                mma16816(O[2*ndp],   pah, bl4 + 0);
                mma16816(O[2*ndp+1], pah, bh4 + 2);
                mma16816(O[2*ndp+1], pal, bh4 + 2);
                mma16816(O[2*ndp+1], pah, bl4 + 2);
            }
        }
        __syncthreads();
    }

    float i0 = 1.f / l0, i1 = 1.f / l1;
    size_t mrow0 = (size_t)(b * T_ + q0 + w * 16 + gid);
    #pragma unroll
    for (int nd = 0; nd < 8; nd++) {
        int col = h * 64 + nd * 8 + 2 * tg;
        float v0 = O[nd][0] * i0, v1 = O[nd][1] * i0;
        float v2 = O[nd][2] * i1, v3 = O[nd][3] * i1;
        float h0 = hf(v0), h1 = hf(v1), h2 = hf(v2), h3 = hf(v3);
        *(uint32_t*)(oh + mrow0 * D_ + col)       = packh(h0, h1);
        *(uint32_t*)(ol + mrow0 * D_ + col)       = packh(v0 - h0, v1 - h1);
        *(uint32_t*)(oh + (mrow0 + 8) * D_ + col) = packh(h2, h3);
        *(uint32_t*)(ol + (mrow0 + 8) * D_ + col) = packh(v2 - h2, v3 - h3);
    }
}

// ---------------------------------------------------------------------------
// Logits
// ---------------------------------------------------------------------------
__global__ void __launch_bounds__(256)
logits_k(const float* __restrict__ xf, const float* __restrict__ wte,
         float* __restrict__ out) {
    __shared__ float xs[B_ * D_];
    int tid = threadIdx.x;
    #pragma unroll
    for (int p = 0; p < 8; p++) {
        int i4 = tid + p * 256;
        float4 v = ((const float4*)xf)[i4];
        xs[i4 * 4 + 0] = v.x; xs[i4 * 4 + 1] = v.y;
        xs[i4 * 4 + 2] = v.z; xs[i4 * 4 + 3] = v.w;
    }
    __syncthreads();
    int n = blockIdx.x * 256 + tid;
    if (n >= V_) return;
    const float* wr = wte + (size_t)n * D_;
    float acc[8] = {0.f, 0.f, 0.f, 0.f, 0.f, 0.f, 0.f, 0.f};
    for (int k = 0; k < D_; k += 4) {
        float4 w = *(const float4*)(wr + k);
        #pragma unroll
        for (int b2 = 0; b2 < 8; b2++) {
            const float* xb = xs + b2 * D_ + k;
            acc[b2] += w.x * xb[0] + w.y * xb[1] + w.z * xb[2] + w.w * xb[3];
        }
    }
    #pragma unroll
    for (int b2 = 0; b2 < 8; b2++) out[(size_t)b2 * V_ + n] = acc[b2];
}

// ---------------------------------------------------------------------------
// Host orchestration
// ---------------------------------------------------------------------------
extern "C" void kernel_launch(void* const* d_in, const int* in_sizes, int n_in,
                              void* d_out, int out_size) {
    const int*   tokens   = (const int*)  d_in[0];
    const float* wte      = (const float*)d_in[1];
    const float* c_attn_w = (const float*)d_in[2];
    const float* c_attn_b = (const float*)d_in[3];
    const float* c_proj_w = (const float*)d_in[4];
    const float* c_proj_b = (const float*)d_in[5];
    const float* ln1_w    = (const float*)d_in[6];
    const float* ln1_b    = (const float*)d_in[7];
    const float* ln2_w    = (const float*)d_in[8];
    const float* ln2_b    = (const float*)d_in[9];
    const float* w1       = (const float*)d_in[10];
    const float* w3       = (const float*)d_in[11];
    const float* w2       = (const float*)d_in[12];
    const float* lnf_w    = (const float*)d_in[13];
    const float* lnf_b    = (const float*)d_in[14];
    float* out = (float*)d_out;

    float *x, *xf;
    cudaGetSymbolAddress((void**)&x,  g_x);
    cudaGetSymbolAddress((void**)&xf, g_xf);

    __half *ah, *al, *uh, *ul, *qh, *ql, *kh, *kl, *vh, *vl;
    cudaGetSymbolAddress((void**)&ah, g_ah);
    cudaGetSymbolAddress((void**)&al, g_al);
    cudaGetSymbolAddress((void**)&uh, g_uh);
    cudaGetSymbolAddress((void**)&ul, g_ul);
    cudaGetSymbolAddress((void**)&qh, g_qh);
    cudaGetSymbolAddress((void**)&ql, g_ql);
    cudaGetSymbolAddress((void**)&kh, g_kh);
    cudaGetSymbolAddress((void**)&kl, g_kl);
    cudaGetSymbolAddress((void**)&vh, g_vh);
    cudaGetSymbolAddress((void**)&vl, g_vl);

    __half *wch, *wcl, *wph, *wpl, *w1h, *w1l, *w3h, *w3l, *w2h, *w2l;
    cudaGetSymbolAddress((void**)&wch, g_wch);
    cudaGetSymbolAddress((void**)&wcl, g_wcl);
    cudaGetSymbolAddress((void**)&wph, g_wph);
    cudaGetSymbolAddress((void**)&wpl, g_wpl);
    cudaGetSymbolAddress((void**)&w1h, g_w1h);
    cudaGetSymbolAddress((void**)&w1l, g_w1l);
    cudaGetSymbolAddress((void**)&w3h, g_w3h);
    cudaGetSymbolAddress((void**)&w3l, g_w3l);
    cudaGetSymbolAddress((void**)&w2h, g_w2h);
    cudaGetSymbolAddress((void**)&w2l, g_w2l);

    const int SMEM = 2 * STAGE_BYTES;   // 81920
    cudaFuncSetAttribute(hgemm16, cudaFuncAttributeMaxDynamicSharedMemorySize, SMEM);
    cudaFuncSetAttribute(hgemm16_qkv, cudaFuncAttributeMaxDynamicSharedMemorySize, SMEM);
    cudaFuncSetAttribute(hgemm16_glu, cudaFuncAttributeMaxDynamicSharedMemorySize, SMEM);
    cudaFuncSetAttribute(mma_attn, cudaFuncAttributeMaxDynamicSharedMemorySize, ATT_SMEM);

    wcvt_all_k<<<(int)(WTOT / 256), 256>>>(
        c_attn_w, c_proj_w, w1, w3, w2,
        wch, wcl, wph, wpl, w1h, w1l, w3h, w3l, w2h, w2l);

    embed_k<<<M_, 256>>>(tokens, wte, x);

    for (int l = 0; l < L_; l++) {
        ln_cvt_k<<<M_, 256>>>(x, ln1_w + l * D_, ln1_b + l * D_, ah, al);
        hgemm16_qkv<<<dim3(3 * D_ / 128, M_ / 128), 128, SMEM>>>(
            ah, al, wch + (size_t)l * 3 * D_ * D_, wcl + (size_t)l * 3 * D_ * D_,
            c_attn_b + l * 3 * D_, qh, ql, kh, kl, vh, vl);
        mma_attn<<<dim3(T_ / 64, NH_, B_), 128, ATT_SMEM>>>(
            qh, ql, kh, kl, vh, vl, ah, al);
        hgemm16<<<dim3(D_ / 128, M_ / 128), 128, SMEM>>>(
            ah, al, wph + (size_t)l * D_ * D_, wpl + (size_t)l * D_ * D_,
            c_proj_b + l * D_, x, M_, D_, D_, 1);
        ln_cvt_k<<<M_, 256>>>(x, ln2_w + l * D_, ln2_b + l * D_, ah, al);
        hgemm16_glu<<<dim3(HID_ / 64, M_ / 128), 128, SMEM>>>(
            ah, al, w1h + (size_t)l * HID_ * D_, w1l + (size_t)l * HID_ * D_,
            w3h + (size_t)l * HID_ * D_, w3l + (size_t)l * HID_ * D_, uh, ul);
        hgemm16<<<dim3(D_ / 128, M_ / 128), 128, SMEM>>>(
            uh, ul, w2h + (size_t)l * D_ * HID_, w2l + (size_t)l * D_ * HID_,
            nullptr, x, M_, D_, HID_, 1);
    }

    ln_k<<<B_, 256>>>(x + (size_t)(T_ - 1) * D_, lnf_w, lnf_b, xf, T_ * D_);
    logits_k<<<(V_ + 255) / 256, 256>>>(xf, wte, out);
}

// round 14
// speedup vs baseline: 1.5478x; 1.5478x over previous
#include <cuda_runtime.h>
#include <cuda_fp16.h>
#include <math.h>
#include <stdint.h>

// Problem dims
#define L_   12
#define D_   1024
#define NH_  16
#define HD_  64
#define HID_ 2816
#define V_   50257
#define B_   8
#define T_   1024
#define M_   (B_*T_)        // 8192 tokens

// ---------------------------------------------------------------------------
// Scratch (static device globals — no allocations allowed)
// ---------------------------------------------------------------------------
__device__ float g_x  [M_ * D_];        // residual stream
__device__ float g_xf [B_ * D_];        // final-ln rows

__device__ __half g_ah[M_ * D_];        // LN / attention outputs (M x D)
__device__ __half g_al[M_ * D_];
__device__ __half g_uh[M_ * HID_];      // GLU output (M x HID) — disjoint
__device__ __half g_ul[M_ * HID_];

__device__ __half g_qh[M_ * D_];
__device__ __half g_ql[M_ * D_];
__device__ __half g_kh[M_ * D_];
__device__ __half g_kl[M_ * D_];
__device__ __half g_vh[M_ * D_];
__device__ __half g_vl[M_ * D_];

__device__ __half g_wch[L_ * 3 * D_ * D_];
__device__ __half g_wcl[L_ * 3 * D_ * D_];
__device__ __half g_wph[L_ * D_ * D_];
__device__ __half g_wpl[L_ * D_ * D_];
__device__ __half g_w1h[L_ * HID_ * D_];
__device__ __half g_w1l[L_ * HID_ * D_];
__device__ __half g_w3h[L_ * HID_ * D_];
__device__ __half g_w3l[L_ * HID_ * D_];
__device__ __half g_w2h[L_ * D_ * HID_];
__device__ __half g_w2l[L_ * D_ * HID_];

// ---------------------------------------------------------------------------
// Helpers
// ---------------------------------------------------------------------------
__device__ __forceinline__ uint32_t smem_u32(const void* p) {
    uint32_t a;
    asm("{ .reg .u64 t; cvta.to.shared.u64 t, %1; cvt.u32.u64 %0, t; }"
        : "=r"(a) : "l"(p));
    return a;
}

__device__ __forceinline__ uint32_t packh(float x, float y) {
    uint32_t r;
    asm("cvt.rn.f16x2.f32 %0, %1, %2;" : "=r"(r) : "f"(y), "f"(x));
    return r;
}

__device__ __forceinline__ float hf(float x) {
    return __half2float(__float2half_rn(x));
}

__device__ __forceinline__ void ldm_x4(uint32_t* r, uint32_t addr) {
    asm volatile("ldmatrix.sync.aligned.m8n8.x4.shared.b16 {%0,%1,%2,%3}, [%4];"
                 : "=r"(r[0]), "=r"(r[1]), "=r"(r[2]), "=r"(r[3]) : "r"(addr));
}
__device__ __forceinline__ void ldm_x4_t(uint32_t* r, uint32_t addr) {
    asm volatile("ldmatrix.sync.aligned.m8n8.x4.trans.shared.b16 {%0,%1,%2,%3}, [%4];"
                 : "=r"(r[0]), "=r"(r[1]), "=r"(r[2]), "=r"(r[3]) : "r"(addr));
}

__device__ __forceinline__ void mma16816(float* c, const uint32_t* a,
                                         const uint32_t* b) {
    asm volatile(
        "mma.sync.aligned.m16n8k16.row.col.f32.f16.f16.f32 "
        "{%0,%1,%2,%3}, {%4,%5,%6,%7}, {%8,%9}, {%0,%1,%2,%3};"
        : "+f"(c[0]), "+f"(c[1]), "+f"(c[2]), "+f"(c[3])
        : "r"(a[0]), "r"(a[1]), "r"(a[2]), "r"(a[3]), "r"(b[0]), "r"(b[1]));
}

__device__ __forceinline__ void cvt8(float4 f0, float4 f1, uint4& hi, uint4& lo) {
    float h0 = hf(f0.x), h1 = hf(f0.y), h2 = hf(f0.z), h3 = hf(f0.w);
    float h4 = hf(f1.x), h5 = hf(f1.y), h6 = hf(f1.z), h7 = hf(f1.w);
    hi.x = packh(h0, h1); hi.y = packh(h2, h3);
    hi.z = packh(h4, h5); hi.w = packh(h6, h7);
    lo.x = packh(f0.x - h0, f0.y - h1);
    lo.y = packh(f0.z - h2, f0.w - h3);
    lo.z = packh(f1.x - h4, f1.y - h5);
    lo.w = packh(f1.z - h6, f1.w - h7);
}

__device__ __forceinline__ void cpa16(uint32_t d, const void* s) {
    asm volatile("cp.async.cg.shared.global [%0], [%1], 16;" :: "r"(d), "l"(s));
}
__device__ __forceinline__ void cpcommit() {
    asm volatile("cp.async.commit_group;");
}
template <int N>
__device__ __forceinline__ void cpwait() {
    asm volatile("cp.async.wait_group %0;" :: "n"(N));
}

// ---------------------------------------------------------------------------
// Fused weight converter
// ---------------------------------------------------------------------------
#define WN0 4718592L
#define WN1 1572864L
#define WN2 4325376L
#define WTOT (WN0 + WN1 + 3 * WN2)

__global__ void wcvt_all_k(const float* __restrict__ cw, const float* __restrict__ pw,
                           const float* __restrict__ w1, const float* __restrict__ w3,
                           const float* __restrict__ w2,
                           __half* cwh, __half* cwl, __half* pwh, __half* pwl,
                           __half* w1h, __half* w1l, __half* w3h, __half* w3l,
                           __half* w2h, __half* w2l) {
    long i = (long)blockIdx.x * 256 + threadIdx.x;
    const float* src; __half* hi; __half* lo;
    if (i < WN0)              { src = cw; hi = cwh; lo = cwl; }
    else if ((i -= WN0) < WN1){ src = pw; hi = pwh; lo = pwl; }
    else if ((i -= WN1) < WN2){ src = w1; hi = w1h; lo = w1l; }
    else if ((i -= WN2) < WN2){ src = w3; hi = w3h; lo = w3l; }
    else { i -= WN2;            src = w2; hi = w2h; lo = w2l; }
    float4 f0 = ((const float4*)src)[i * 2];
    float4 f1 = ((const float4*)src)[i * 2 + 1];
    uint4 h, l;
    cvt8(f0, f1, h, l);
    ((uint4*)hi)[i] = h;
    ((uint4*)lo)[i] = l;
}

// ---------------------------------------------------------------------------
// GEMM mainloop — exact R11 structure (proven 24.47 ms), plus compile-time
// TERMS: 3 = full compensation (hh, lh, hl); 2 = drop W-lo term (a * bh),
// also skipping the Wlo cp.async and LDSM. Used only for the GLU GEMM.
// ---------------------------------------------------------------------------
#define RSTRIDE 80
#define STAGE_BYTES 40960

struct LoaderPtrs {
    const __half *pa0, *pal0, *pa1, *pal1;
    const __half *pw0, *pwl0, *pw1, *pwl1;
};

template <int TERMS>
__device__ __forceinline__ void gemm_mainloop(
    uint32_t sb, char* sm, int tid, int K, const LoaderPtrs& P,
    const uint32_t* arow, const uint32_t* brow, float acc[4][4][4]) {
    const int r0l = tid >> 2, c0l = tid & 3;
    const int r1l = (tid + 256) >> 2;

    auto load_stage = [&](int s, int kc) {
        uint32_t base = sb + (uint32_t)s * STAGE_BYTES;
        {
            uint32_t d = base + (uint32_t)(r0l * RSTRIDE + c0l * 16);
            cpa16(d +     0, P.pa0  + kc);
            cpa16(d + 10240, P.pal0 + kc);
            cpa16(d + 20480, P.pw0  + kc);
            if (TERMS >= 3) cpa16(d + 30720, P.pwl0 + kc);
        }
        {
            uint32_t d = base + (uint32_t)(r1l * RSTRIDE + c0l * 16);
            cpa16(d +     0, P.pa1  + kc);
            cpa16(d + 10240, P.pal1 + kc);
            cpa16(d + 20480, P.pw1  + kc);
            if (TERMS >= 3) cpa16(d + 30720, P.pwl1 + kc);
        }
    };

    const int nc = K >> 5;
    load_stage(0, 0);
    cpcommit();

    for (int j = 0; j < nc; j++) {
        cpwait<0>();          // own cp.async for stage j complete
        __syncthreads();      // publish stage j; all warps done with other buffer
        if (j + 1 < nc) {
            load_stage((j + 1) & 1, (j + 1) << 5);
            cpcommit();
        }

        const uint32_t base = sb + (uint32_t)(j & 1) * STAGE_BYTES;
        #pragma unroll
        for (int ks = 0; ks < 2; ks++) {
            const uint32_t ko = (uint32_t)(ks * 32);
            uint32_t bh[4][2], bl[4][2];
            #pragma unroll
            for (int p = 0; p < 2; p++) {
                uint32_t t4[4];
                ldm_x4(t4, base + 20480 + brow[p] + ko);
                bh[2*p][0] = t4[0]; bh[2*p][1] = t4[1];
                bh[2*p+1][0] = t4[2]; bh[2*p+1][1] = t4[3];
                if (TERMS >= 3) {
                    ldm_x4(t4, base + 30720 + brow[p] + ko);
                    bl[2*p][0] = t4[0]; bl[2*p][1] = t4[1];
                    bl[2*p+1][0] = t4[2]; bl[2*p+1][1] = t4[3];
                }
            }
            uint32_t ahb[2][4], alb[2][4];
            ldm_x4(ahb[0], base +     0 + arow[0] + ko);
            ldm_x4(alb[0], base + 10240 + arow[0] + ko);
            #pragma unroll
            for (int mt = 0; mt < 4; mt++) {
                const int cur = mt & 1;
                if (mt < 3) {
                    ldm_x4(ahb[cur ^ 1], base +     0 + arow[mt + 1] + ko);
                    ldm_x4(alb[cur ^ 1], base + 10240 + arow[mt + 1] + ko);
                }
                #pragma unroll
                for (int nt = 0; nt < 4; nt++)
                    mma16816(acc[mt][nt], ahb[cur], bh[nt]);
                #pragma unroll
                for (int nt = 0; nt < 4; nt++)
                    mma16816(acc[mt][nt], alb[cur], bh[nt]);
                if (TERMS >= 3) {
                    #pragma unroll
                    for (int nt = 0; nt < 4; nt++)
                        mma16816(acc[mt][nt], ahb[cur], bl[nt]);
                }
            }
        }
    }
    __syncthreads();   // protect smem-reusing epilogues
}

#define GEMM_PROLOG                                                            \
    extern __shared__ __align__(16) char sm[];                                 \
    const uint32_t sb = smem_u32(sm);                                          \
    const int tid = threadIdx.x;                                               \
    const int warp = tid >> 5, lane = tid & 31;                                \
    const int wm = warp & 1, wn = warp >> 1;                                   \
    const int gid = lane >> 2, tg = lane & 3;                                  \
    const int l15 = lane & 15, l16 = (lane >> 4) & 1;                          \
    const int l7 = lane & 7, l8 = (lane >> 3) & 1;                             \
    uint32_t arow[4], brow[2];                                                 \
    _Pragma("unroll")                                                          \
    for (int mt = 0; mt < 4; mt++)                                             \
        arow[mt] = (uint32_t)((wm * 64 + mt * 16 + l15) * RSTRIDE + l16 * 16); \
    _Pragma("unroll")                                                          \
    for (int p = 0; p < 2; p++)                                                \
        brow[p] = (uint32_t)((wn * 32 + p * 16 + l7 + l16 * 8) * RSTRIDE + l8 * 16); \
    float acc[4][4][4];                                                        \
    _Pragma("unroll")                                                          \
    for (int i = 0; i < 4; i++)                                                \
        _Pragma("unroll")                                                      \
        for (int j = 0; j < 4; j++)                                            \
            _Pragma("unroll")                                                  \
            for (int c = 0; c < 4; c++) acc[i][j][c] = 0.f;                    \
    const int r0l = tid >> 2, c0l = tid & 3;                                   \
    const int r1l = (tid + 256) >> 2;

// ---------------------------------------------------------------------------
// Standard GEMM "NT" (proj / w2): C = A@W^T (+bias)(+residual). 3-term.
// ---------------------------------------------------------------------------
__global__ void __launch_bounds__(256, 2)
hgemm16(const __half* __restrict__ a_hi, const __half* __restrict__ a_lo,
        const __half* __restrict__ w_hi, const __half* __restrict__ w_lo,
        const float* __restrict__ bias, float* __restrict__ C,
        int M, int N, int K, int residual) {
    GEMM_PROLOG
    const int by = blockIdx.y * 128, bx = blockIdx.x * 128;
    LoaderPtrs P;
    P.pa0  = a_hi + (size_t)(by + r0l) * K + c0l * 8;
    P.pal0 = a_lo + (size_t)(by + r0l) * K + c0l * 8;
    P.pa1  = a_hi + (size_t)(by + r1l) * K + c0l * 8;
    P.pal1 = a_lo + (size_t)(by + r1l) * K + c0l * 8;
    P.pw0  = w_hi + (size_t)(bx + r0l) * K + c0l * 8;
    P.pwl0 = w_lo + (size_t)(bx + r0l) * K + c0l * 8;
    P.pw1  = w_hi + (size_t)(bx + r1l) * K + c0l * 8;
    P.pwl1 = w_lo + (size_t)(bx + r1l) * K + c0l * 8;
    gemm_mainloop<3>(sb, sm, tid, K, P, arow, brow, acc);

    const size_t mBase = (size_t)by + wm * 64;
    const int    nBase = bx + wn * 32;
    #pragma unroll
    for (int mt = 0; mt < 4; mt++) {
        #pragma unroll
        for (int nt = 0; nt < 4; nt++) {
            int c0 = nBase + nt * 8 + tg * 2;
            float b0 = bias ? bias[c0]     : 0.f;
            float b1 = bias ? bias[c0 + 1] : 0.f;
            size_t r0 = mBase + mt * 16 + gid;
            float* p0 = C + r0 * N + c0;
            float* p1 = C + (r0 + 8) * N + c0;
            float v00 = acc[mt][nt][0] + b0, v01 = acc[mt][nt][1] + b1;
            float v10 = acc[mt][nt][2] + b0, v11 = acc[mt][nt][3] + b1;
            if (residual) { v00 += p0[0]; v01 += p0[1]; v10 += p1[0]; v11 += p1[1]; }
            p0[0] = v00; p0[1] = v01;
            p1[0] = v10; p1[1] = v11;
        }
    }
}

// ---------------------------------------------------------------------------
// QKV GEMM with fused bias + RoPE + fp16 hi/lo split output. 3-term.
// ---------------------------------------------------------------------------
__global__ void __launch_bounds__(256, 2)
hgemm16_qkv(const __half* __restrict__ a_hi, const __half* __restrict__ a_lo,
            const __half* __restrict__ w_hi, const __half* __restrict__ w_lo,
            const float* __restrict__ bias,
            __half* __restrict__ qh, __half* __restrict__ ql,
            __half* __restrict__ kh, __half* __restrict__ kl,
            __half* __restrict__ vh, __half* __restrict__ vl) {
    GEMM_PROLOG
    const int K = D_;
    const int by = blockIdx.y * 128, bx = blockIdx.x * 128;
    LoaderPtrs P;
    P.pa0  = a_hi + (size_t)(by + r0l) * K + c0l * 8;
    P.pal0 = a_lo + (size_t)(by + r0l) * K + c0l * 8;
    P.pa1  = a_hi + (size_t)(by + r1l) * K + c0l * 8;
    P.pal1 = a_lo + (size_t)(by + r1l) * K + c0l * 8;
    P.pw0  = w_hi + (size_t)(bx + r0l) * K + c0l * 8;
    P.pwl0 = w_lo + (size_t)(bx + r0l) * K + c0l * 8;
    P.pw1  = w_hi + (size_t)(bx + r1l) * K + c0l * 8;
    P.pwl1 = w_lo + (size_t)(bx + r1l) * K + c0l * 8;
    gemm_mainloop<3>(sb, sm, tid, K, P, arow, brow, acc);

    // stage fp32 tile (+bias) in smem: [128][132]
    float* smf = (float*)sm;
    #pragma unroll
    for (int mt = 0; mt < 4; mt++) {
        #pragma unroll
        for (int nt = 0; nt < 4; nt++) {
            int col = wn * 32 + nt * 8 + tg * 2;
            int row = wm * 64 + mt * 16 + gid;
            float b0 = bias[bx + col], b1 = bias[bx + col + 1];
            smf[row * 132 + col]           = acc[mt][nt][0] + b0;
            smf[row * 132 + col + 1]       = acc[mt][nt][1] + b1;
            smf[(row + 8) * 132 + col]     = acc[mt][nt][2] + b0;
            smf[(row + 8) * 132 + col + 1] = acc[mt][nt][3] + b1;
        }
    }
    __syncthreads();

    const int region = blockIdx.x >> 3;      // 0 q, 1 k, 2 v
    #pragma unroll 4
    for (int it = 0; it < 16; it++) {
        int idx = tid + it * 256;            // 4096 quads
        int r = idx >> 5;
        int c4 = (idx & 31) * 4;
        int mrow = by + r;
        float4 x4 = *(float4*)&smf[r * 132 + c4];
        float o0, o1, o2, o3;
        __half *dh, *dl;
        int dcol;
        if (region < 2) {
            int cg = bx + c4;
            int hc = cg & 63;
            int hi_half = hc & 32;
            float4 p4 = *(float4*)&smf[r * 132 + (hi_half ? c4 - 32 : c4 + 32)];
            int t = mrow & (T_ - 1);
            float oo[4];
            float xv[4] = {x4.x, x4.y, x4.z, x4.w};
            float pv[4] = {p4.x, p4.y, p4.z, p4.w};
            #pragma unroll
            for (int e = 0; e < 4; e++) {
                int i = (hc & 31) + e;
                float inv = exp2f((float)i * (-13.28771237954945f / 32.0f));
                float ang = (float)t * inv;
                float sn, cs;
                sincosf(ang, &sn, &cs);
                oo[e] = hi_half ? (xv[e] * cs + pv[e] * sn)
                                : (xv[e] * cs - pv[e] * sn);
            }
            if (region == 0) {
                o0 = oo[0] * 0.125f; o1 = oo[1] * 0.125f;
                o2 = oo[2] * 0.125f; o3 = oo[3] * 0.125f;
                dh = qh; dl = ql; dcol = cg;
            } else {
                o0 = oo[0]; o1 = oo[1]; o2 = oo[2]; o3 = oo[3];
                dh = kh; dl = kl; dcol = cg - D_;
            }
        } else {
            o0 = x4.x; o1 = x4.y; o2 = x4.z; o3 = x4.w;
            dh = vh; dl = vl; dcol = bx + c4 - 2 * D_;
        }
        float h0 = hf(o0), h1 = hf(o1), h2 = hf(o2), h3 = hf(o3);
        uint2 hh, ll;
        hh.x = packh(h0, h1); hh.y = packh(h2, h3);
        ll.x = packh(o0 - h0, o1 - h1); ll.y = packh(o2 - h2, o3 - h3);
        *(uint2*)(dh + (size_t)mrow * D_ + dcol) = hh;
        *(uint2*)(dl + (size_t)mrow * D_ + dcol) = ll;
    }
}

// ---------------------------------------------------------------------------
// Fused GLU GEMM — 2-TERM compensation (a*bh): u = A@w1h^T, g = A@w3h^T,
// out = silu(u)*g as fp16 hi/lo. Outputs disjoint from inputs.
// ---------------------------------------------------------------------------
__global__ void __launch_bounds__(256, 2)
hgemm16_glu(const __half* __restrict__ a_hi, const __half* __restrict__ a_lo,
            const __half* __restrict__ w1h, const __half* __restrict__ w1l,
            const __half* __restrict__ w3h, const __half* __restrict__ w3l,
            __half* __restrict__ oh, __half* __restrict__ ol) {
    GEMM_PROLOG
    const int K = D_;
    const int by = blockIdx.y * 128;
    const int bx64 = blockIdx.x * 64;
    LoaderPtrs P;
    P.pa0  = a_hi + (size_t)(by + r0l) * K + c0l * 8;
    P.pal0 = a_lo + (size_t)(by + r0l) * K + c0l * 8;
    P.pa1  = a_hi + (size_t)(by + r1l) * K + c0l * 8;
    P.pal1 = a_lo + (size_t)(by + r1l) * K + c0l * 8;
    // chunk0: B rows 0..63 -> w1 ; chunk1: B rows 64..127 -> w3 (r1l-64 == r0l)
    P.pw0  = w1h + (size_t)(bx64 + r0l) * K + c0l * 8;
    P.pwl0 = w1l + (size_t)(bx64 + r0l) * K + c0l * 8;
    P.pw1  = w3h + (size_t)(bx64 + r0l) * K + c0l * 8;
    P.pwl1 = w3l + (size_t)(bx64 + r0l) * K + c0l * 8;
    gemm_mainloop<2>(sb, sm, tid, K, P, arow, brow, acc);

    // stage fp32 [128][132]: cols 0..63 = u, 64..127 = g
    float* smf = (float*)sm;
    #pragma unroll
    for (int mt = 0; mt < 4; mt++) {
        #pragma unroll
        for (int nt = 0; nt < 4; nt++) {
            int col = wn * 32 + nt * 8 + tg * 2;
            int row = wm * 64 + mt * 16 + gid;
            smf[row * 132 + col]           = acc[mt][nt][0];
            smf[row * 132 + col + 1]       = acc[mt][nt][1];
            smf[(row + 8) * 132 + col]     = acc[mt][nt][2];
            smf[(row + 8) * 132 + col + 1] = acc[mt][nt][3];
        }
    }
    __syncthreads();

    #pragma unroll 4
    for (int it = 0; it < 8; it++) {
        int idx = tid + it * 256;            // 2048 quads (128 x 64 / 4)
        int r = idx >> 4;
        int c4 = (idx & 15) * 4;
        float4 uv = *(float4*)&smf[r * 132 + c4];
        float4 gv = *(float4*)&smf[r * 132 + c4 + 64];
        float o0 = uv.x / (1.f + expf(-uv.x)) * gv.x;
        float o1 = uv.y / (1.f + expf(-uv.y)) * gv.y;
        float o2 = uv.z / (1.f + expf(-uv.z)) * gv.z;
        float o3 = uv.w / (1.f + expf(-uv.w)) * gv.w;
        float h0 = hf(o0), h1 = hf(o1), h2 = hf(o2), h3 = hf(o3);
        uint2 hh, ll;
        hh.x = packh(h0, h1); hh.y = packh(h2, h3);
        ll.x = packh(o0 - h0, o1 - h1); ll.y = packh(o2 - h2, o3 - h3);
        size_t off = (size_t)(by + r) * HID_ + bx64 + c4;
        *(uint2*)(oh + off) = hh;
        *(uint2*)(ol + off) = ll;
    }
}

// ---------------------------------------------------------------------------
// Embedding gather
// ---------------------------------------------------------------------------
__global__ void embed_k(const int* __restrict__ tok, const float* __restrict__ wte,
                        float* __restrict__ x) {
    int m = blockIdx.x;
    int t = tok[m];
    const float4* src = (const float4*)(wte + (size_t)t * D_);
    float4* dst = (float4*)(x + (size_t)m * D_);
    dst[threadIdx.x] = src[threadIdx.x];
}

// ---------------------------------------------------------------------------
// LayerNorm cores
// ---------------------------------------------------------------------------
__device__ __forceinline__ void ln_core(const float* xr, int tid,
                                        float4& v, float& mean, float& rstd) {
    v = ((const float4*)xr)[tid];
    float s = v.x + v.y + v.z + v.w;
    float q = v.x*v.x + v.y*v.y + v.z*v.z + v.w*v.w;
    #pragma unroll
    for (int off = 16; off > 0; off >>= 1) {
        s += __shfl_down_sync(0xffffffffu, s, off);
        q += __shfl_down_sync(0xffffffffu, q, off);
    }
    __shared__ float ss[8], sq[8];
    int wi = tid >> 5, ln = tid & 31;
    if (ln == 0) { ss[wi] = s; sq[wi] = q; }
    __syncthreads();
    if (tid == 0) {
        float a = 0.f, c = 0.f;
        #pragma unroll
        for (int i = 0; i < 8; i++) { a += ss[i]; c += sq[i]; }
        ss[0] = a; sq[0] = c;
    }
    __syncthreads();
    mean = ss[0] * (1.f / D_);
    float var = sq[0] * (1.f / D_) - mean * mean;
    rstd = rsqrtf(var + 1e-5f);
}

__global__ void ln_k(const float* __restrict__ x, const float* __restrict__ w,
                     const float* __restrict__ b, float* __restrict__ o,
                     int rowStride) {
    int row = blockIdx.x, tid = threadIdx.x;
    float4 v; float mean, rstd;
    ln_core(x + (size_t)row * rowStride, tid, v, mean, rstd);
    float4 wv = ((const float4*)w)[tid];
    float4 bv = ((const float4*)b)[tid];
    float4 ov;
    ov.x = (v.x - mean) * rstd * wv.x + bv.x;
    ov.y = (v.y - mean) * rstd * wv.y + bv.y;
    ov.z = (v.z - mean) * rstd * wv.z + bv.z;
    ov.w = (v.w - mean) * rstd * wv.w + bv.w;
    ((float4*)(o + (size_t)row * D_))[tid] = ov;
}

__global__ void ln_cvt_k(const float* __restrict__ x, const float* __restrict__ w,
                         const float* __restrict__ b, __half* __restrict__ hi,
                         __half* __restrict__ lo) {
    int row = blockIdx.x, tid = threadIdx.x;
    float4 v; float mean, rstd;
    ln_core(x + (size_t)row * D_, tid, v, mean, rstd);
    float4 wv = ((const float4*)w)[tid];
    float4 bv = ((const float4*)b)[tid];
    float o0 = (v.x - mean) * rstd * wv.x + bv.x;
    float o1 = (v.y - mean) * rstd * wv.y + bv.y;
    float o2 = (v.z - mean) * rstd * wv.z + bv.z;
    float o3 = (v.w - mean) * rstd * wv.w + bv.w;
    size_t ob = (size_t)row * D_ + tid * 4;
    float h0 = hf(o0), h1 = hf(o1), h2 = hf(o2), h3 = hf(o3);
    uint2 hh, ll;
    hh.x = packh(h0, h1); hh.y = packh(h2, h3);
    ll.x = packh(o0 - h0, o1 - h1); ll.y = packh(o2 - h2, o3 - h3);
    *(uint2*)(hi + ob) = hh;
    *(uint2*)(lo + ob) = ll;
}

// ---------------------------------------------------------------------------
// MMA flash attention (proven R7 kernel, unchanged)
// ---------------------------------------------------------------------------
#define ARS 72
#define ATT_SMEM 92160

__global__ void __launch_bounds__(128)
mma_attn(const __half* __restrict__ qh, const __half* __restrict__ ql,
         const __half* __restrict__ kh, const __half* __restrict__ kl,
         const __half* __restrict__ vh, const __half* __restrict__ vl,
         __half* __restrict__ oh, __half* __restrict__ ol) {
    extern __shared__ __align__(16) __half sa[];
    const int qt = blockIdx.x, h = blockIdx.y, b = blockIdx.z;
    const int q0 = qt * 64;
    const int tid = threadIdx.x, w = tid >> 5, lane = tid & 31;
    const int gid = lane >> 2, tg = lane & 3;
    const int l7 = lane & 7, l8 = (lane >> 3) & 1, l16 = (lane >> 4) & 1;
    const uint32_t sb = smem_u32(sa);

    const int QHI = 0, QLO = 4608, STG = 9216, STGSZ = 18432;

    for (int i = tid; i < 1024; i += 128) {
        int arr = i >> 9, rem = i & 511, row = rem >> 3, ch = rem & 7;
        const __half* src = (arr ? ql : qh) +
            (size_t)(b * T_ + q0 + row) * D_ + h * 64 + ch * 8;
        *(uint4*)(sa + (arr ? QLO : QHI) + row * ARS + ch * 8) = *(const uint4*)src;
    }

    auto load_kv = [&](int s, int kt) {
        const __half* srcs[4] = {kh, kl, vh, vl};
        int base0 = STG + s * STGSZ;
        for (int i = tid; i < 2048; i += 128) {
            int arr = i >> 9, rem = i & 511, row = rem >> 3, ch = rem & 7;
            const __half* src = srcs[arr] +
                (size_t)(b * T_ + kt * 64 + row) * D_ + h * 64 + ch * 8;
            uint32_t dst = sb + (uint32_t)(base0 + arr * 4608 + row * ARS + ch * 8) * 2;
            cpa16(dst, src);
        }
    };

    load_kv(0, 0);
    cpcommit();
    __syncthreads();

    uint32_t aqh[4][4], aql[4][4];
    {
        uint32_t abase = sb + (uint32_t)((w * 16 + (lane & 15)) * ARS + l16 * 8) * 2;
        #pragma unroll
        for (int kc = 0; kc < 4; kc++) {
            ldm_x4(aqh[kc], abase + kc * 32);
            ldm_x4(aql[kc], abase + 9216 + kc * 32);
        }
    }

    float m0 = -1e30f, m1 = -1e30f, l0 = 0.f, l1 = 0.f;
    float O[8][4];
    #pragma unroll
    for (int n = 0; n < 8; n++)
        #pragma unroll
        for (int c = 0; c < 4; c++) O[n][c] = 0.f;

    const int nt = qt + 1;
    for (int kt = 0; kt < nt; kt++) {
        const int s = kt & 1;
        if (kt + 1 < nt) { load_kv(s ^ 1, kt + 1); cpcommit(); cpwait<1>(); }
        else             { cpwait<0>(); }
        __syncthreads();

        const uint32_t kbase = sb + (uint32_t)(STG + s * STGSZ) * 2;

        float S[8][4];
        #pragma unroll
        for (int n = 0; n < 8; n++)
            #pragma unroll
            for (int c = 0; c < 4; c++) S[n][c] = 0.f;

        #pragma unroll
        for (int kc = 0; kc < 4; kc++) {
            #pragma unroll
            for (int np = 0; np < 4; np++) {
                uint32_t addr = kbase +
                    (uint32_t)((np * 16 + l7 + l16 * 8) * ARS) * 2 + l8 * 16 + kc * 32;
                uint32_t bh4[4], bl4[4];
                ldm_x4(bh4, addr);
                ldm_x4(bl4, addr + 9216);
                mma16816(S[2*np],   aqh[kc], bh4 + 0);
                mma16816(S[2*np],   aql[kc], bh4 + 0);
                mma16816(S[2*np],   aqh[kc], bl4 + 0);
                mma16816(S[2*np+1], aqh[kc], bh4 + 2);
                mma16816(S[2*np+1], aql[kc], bh4 + 2);
                mma16816(S[2*np+1], aqh[kc], bl4 + 2);
            }
        }

        if (kt == qt) {
            #pragma unroll
            for (int n = 0; n < 8; n++)
                #pragma unroll
                for (int c = 0; c < 4; c++) {
                    int qg = w * 16 + gid + (c >> 1) * 8;
                    int kg = n * 8 + 2 * tg + (c & 1);
                    if (kg > qg) S[n][c] = -1e30f;
                }
        }

        float mt0 = -1e30f, mt1 = -1e30f;
        #pragma unroll
        for (int n = 0; n < 8; n++) {
            mt0 = fmaxf(mt0, fmaxf(S[n][0], S[n][1]));
            mt1 = fmaxf(mt1, fmaxf(S[n][2], S[n][3]));
        }
        mt0 = fmaxf(mt0, __shfl_xor_sync(0xffffffffu, mt0, 1));
        mt0 = fmaxf(mt0, __shfl_xor_sync(0xffffffffu, mt0, 2));
        mt1 = fmaxf(mt1, __shfl_xor_sync(0xffffffffu, mt1, 1));
        mt1 = fmaxf(mt1, __shfl_xor_sync(0xffffffffu, mt1, 2));
        float mn0 = fmaxf(m0, mt0), mn1 = fmaxf(m1, mt1);
        float a0 = expf(m0 - mn0), a1 = expf(m1 - mn1);
        float ps0 = 0.f, ps1 = 0.f;
        #pragma unroll
        for (int n = 0; n < 8; n++) {
            S[n][0] = expf(S[n][0] - mn0); ps0 += S[n][0];
            S[n][1] = expf(S[n][1] - mn0); ps0 += S[n][1];
            S[n][2] = expf(S[n][2] - mn1); ps1 += S[n][2];
            S[n][3] = expf(S[n][3] - mn1); ps1 += S[n][3];
        }
        ps0 += __shfl_xor_sync(0xffffffffu, ps0, 1);
        ps0 += __shfl_xor_sync(0xffffffffu, ps0, 2);
        ps1 += __shfl_xor_sync(0xffffffffu, ps1, 1);
        ps1 += __shfl_xor_sync(0xffffffffu, ps1, 2);
        l0 = l0 * a0 + ps0; l1 = l1 * a1 + ps1;
        m0 = mn0; m1 = mn1;
        #pragma unroll
        for (int n = 0; n < 8; n++) {
            O[n][0] *= a0; O[n][1] *= a0;
            O[n][2] *= a1; O[n][3] *= a1;
        }

        const uint32_t vbase = kbase + 18432;
        #pragma unroll
        for (int kc = 0; kc < 4; kc++) {
            float p0 = S[2*kc][0],   p1 = S[2*kc][1];
            float p2 = S[2*kc][2],   p3 = S[2*kc][3];
            float r0 = S[2*kc+1][0], r1 = S[2*kc+1][1];
            float r2 = S[2*kc+1][2], r3 = S[2*kc+1][3];
            float hp0 = hf(p0), hp1 = hf(p1), hp2 = hf(p2), hp3 = hf(p3);
            float hr0 = hf(r0), hr1 = hf(r1), hr2 = hf(r2), hr3 = hf(r3);
            uint32_t pah[4], pal[4];
            pah[0] = packh(hp0, hp1); pah[1] = packh(hp2, hp3);
            pah[2] = packh(hr0, hr1); pah[3] = packh(hr2, hr3);
            pal[0] = packh(p0 - hp0, p1 - hp1); pal[1] = packh(p2 - hp2, p3 - hp3);
            pal[2] = packh(r0 - hr0, r1 - hr1); pal[3] = packh(r2 - hr2, r3 - hr3);
            #pragma unroll
            for (int ndp = 0; ndp < 4; ndp++) {
                uint32_t addr = vbase +
                    (uint32_t)((kc * 16 + l7 + l8 * 8) * ARS) * 2 + ndp * 32 + l16 * 16;
                uint32_t bh4[4], bl4[4];
                ldm_x4_t(bh4, addr);
                ldm_x4_t(bl4, addr + 9216);
                mma16816(O[2*ndp],   pah, bh4 + 0);
                mma16816(O[2*ndp],   pal, bh4 + 0);
                mma16816(O[2*ndp],   pah, bl4 + 0);
                mma16816(O[2*ndp+1], pah, bh4 + 2);
                mma16816(O[2*ndp+1], pal, bh4 + 2);
                mma16816(O[2*ndp+1], pah, bl4 + 2);
            }
        }
        __syncthreads();
    }

    float i0 = 1.f / l0, i1 = 1.f / l1;
    size_t mrow0 = (size_t)(b * T_ + q0 + w * 16 + gid);
    #pragma unroll
    for (int nd = 0; nd < 8; nd++) {
        int col = h * 64 + nd * 8 + 2 * tg;
        float v0 = O[nd][0] * i0, v1 = O[nd][1] * i0;
        float v2 = O[nd][2] * i1, v3 = O[nd][3] * i1;
        float h0 = hf(v0), h1 = hf(v1), h2 = hf(v2), h3 = hf(v3);
        *(uint32_t*)(oh + mrow0 * D_ + col)       = packh(h0, h1);
        *(uint32_t*)(ol + mrow0 * D_ + col)       = packh(v0 - h0, v1 - h1);
        *(uint32_t*)(oh + (mrow0 + 8) * D_ + col) = packh(h2, h3);
        *(uint32_t*)(ol + (mrow0 + 8) * D_ + col) = packh(v2 - h2, v3 - h3);
    }
}

// ---------------------------------------------------------------------------
// Logits
// ---------------------------------------------------------------------------
__global__ void __launch_bounds__(256)
logits_k(const float* __restrict__ xf, const float* __restrict__ wte,
         float* __restrict__ out) {
    __shared__ float xs[B_ * D_];
    int tid = threadIdx.x;
    #pragma unroll
    for (int p = 0; p < 8; p++) {
        int i4 = tid + p * 256;
        float4 v = ((const float4*)xf)[i4];
        xs[i4 * 4 + 0] = v.x; xs[i4 * 4 + 1] = v.y;
        xs[i4 * 4 + 2] = v.z; xs[i4 * 4 + 3] = v.w;
    }
    __syncthreads();
    int n = blockIdx.x * 256 + tid;
    if (n >= V_) return;
    const float* wr = wte + (size_t)n * D_;
    float acc[8] = {0.f, 0.f, 0.f, 0.f, 0.f, 0.f, 0.f, 0.f};
    for (int k = 0; k < D_; k += 4) {
        float4 w = *(const float4*)(wr + k);
        #pragma unroll
        for (int b2 = 0; b2 < 8; b2++) {
            const float* xb = xs + b2 * D_ + k;
            acc[b2] += w.x * xb[0] + w.y * xb[1] + w.z * xb[2] + w.w * xb[3];
        }
    }
    #pragma unroll
    for (int b2 = 0; b2 < 8; b2++) out[(size_t)b2 * V_ + n] = acc[b2];
}

// ---------------------------------------------------------------------------
// Host orchestration
// ---------------------------------------------------------------------------
extern "C" void kernel_launch(void* const* d_in, const int* in_sizes, int n_in,
                              void* d_out, int out_size) {
    const int*   tokens   = (const int*)  d_in[0];
    const float* wte      = (const float*)d_in[1];
    const float* c_attn_w = (const float*)d_in[2];
    const float* c_attn_b = (const float*)d_in[3];
    const float* c_proj_w = (const float*)d_in[4];
    const float* c_proj_b = (const float*)d_in[5];
    const float* ln1_w    = (const float*)d_in[6];
    const float* ln1_b    = (const float*)d_in[7];
    const float* ln2_w    = (const float*)d_in[8];
    const float* ln2_b    = (const float*)d_in[9];
    const float* w1       = (const float*)d_in[10];
    const float* w3       = (const float*)d_in[11];
    const float* w2       = (const float*)d_in[12];
    const float* lnf_w    = (const float*)d_in[13];
    const float* lnf_b    = (const float*)d_in[14];
    float* out = (float*)d_out;

    float *x, *xf;
    cudaGetSymbolAddress((void**)&x,  g_x);
    cudaGetSymbolAddress((void**)&xf, g_xf);

    __half *ah, *al, *uh, *ul, *qh, *ql, *kh, *kl, *vh, *vl;
    cudaGetSymbolAddress((void**)&ah, g_ah);
    cudaGetSymbolAddress((void**)&al, g_al);
    cudaGetSymbolAddress((void**)&uh, g_uh);
    cudaGetSymbolAddress((void**)&ul, g_ul);
    cudaGetSymbolAddress((void**)&qh, g_qh);
    cudaGetSymbolAddress((void**)&ql, g_ql);
    cudaGetSymbolAddress((void**)&kh, g_kh);
    cudaGetSymbolAddress((void**)&kl, g_kl);
    cudaGetSymbolAddress((void**)&vh, g_vh);
    cudaGetSymbolAddress((void**)&vl, g_vl);

    __half *wch, *wcl, *wph, *wpl, *w1h, *w1l, *w3h, *w3l, *w2h, *w2l;
    cudaGetSymbolAddress((void**)&wch, g_wch);
    cudaGetSymbolAddress((void**)&wcl, g_wcl);
    cudaGetSymbolAddress((void**)&wph, g_wph);
    cudaGetSymbolAddress((void**)&wpl, g_wpl);
    cudaGetSymbolAddress((void**)&w1h, g_w1h);
    cudaGetSymbolAddress((void**)&w1l, g_w1l);
    cudaGetSymbolAddress((void**)&w3h, g_w3h);
    cudaGetSymbolAddress((void**)&w3l, g_w3l);
    cudaGetSymbolAddress((void**)&w2h, g_w2h);
    cudaGetSymbolAddress((void**)&w2l, g_w2l);

    const int SMEM = 2 * STAGE_BYTES;
    cudaFuncSetAttribute(hgemm16, cudaFuncAttributeMaxDynamicSharedMemorySize, SMEM);
    cudaFuncSetAttribute(hgemm16_qkv, cudaFuncAttributeMaxDynamicSharedMemorySize, SMEM);
    cudaFuncSetAttribute(hgemm16_glu, cudaFuncAttributeMaxDynamicSharedMemorySize, SMEM);
    cudaFuncSetAttribute(mma_attn, cudaFuncAttributeMaxDynamicSharedMemorySize, ATT_SMEM);

    wcvt_all_k<<<(int)(WTOT / 256), 256>>>(
        c_attn_w, c_proj_w, w1, w3, w2,
        wch, wcl, wph, wpl, w1h, w1l, w3h, w3l, w2h, w2l);

    embed_k<<<M_, 256>>>(tokens, wte, x);

    for (int l = 0; l < L_; l++) {
        ln_cvt_k<<<M_, 256>>>(x, ln1_w + l * D_, ln1_b + l * D_, ah, al);
        hgemm16_qkv<<<dim3(3 * D_ / 128, M_ / 128), 256, SMEM>>>(
            ah, al, wch + (size_t)l * 3 * D_ * D_, wcl + (size_t)l * 3 * D_ * D_,
            c_attn_b + l * 3 * D_, qh, ql, kh, kl, vh, vl);
        mma_attn<<<dim3(T_ / 64, NH_, B_), 128, ATT_SMEM>>>(
            qh, ql, kh, kl, vh, vl, ah, al);
        hgemm16<<<dim3(D_ / 128, M_ / 128), 256, SMEM>>>(
            ah, al, wph + (size_t)l * D_ * D_, wpl + (size_t)l * D_ * D_,
            c_proj_b + l * D_, x, M_, D_, D_, 1);
        ln_cvt_k<<<M_, 256>>>(x, ln2_w + l * D_, ln2_b + l * D_, ah, al);
        hgemm16_glu<<<dim3(HID_ / 64, M_ / 128), 256, SMEM>>>(
            ah, al, w1h + (size_t)l * HID_ * D_, w1l + (size_t)l * HID_ * D_,
            w3h + (size_t)l * HID_ * D_, w3l + (size_t)l * HID_ * D_, uh, ul);
        hgemm16<<<dim3(D_ / 128, M_ / 128), 256, SMEM>>>(
            uh, ul, w2h + (size_t)l * D_ * HID_, w2l + (size_t)l * D_ * HID_,
            nullptr, x, M_, D_, HID_, 1);
    }

    ln_k<<<B_, 256>>>(x + (size_t)(T_ - 1) * D_, lnf_w, lnf_b, xf, T_ * D_);
    logits_k<<<(V_ + 255) / 256, 256>>>(xf, wte, out);
}

// round 15
// speedup vs baseline: 1.7039x; 1.1009x over previous
#include <cuda_runtime.h>
#include <cuda_fp16.h>
#include <math.h>
#include <stdint.h>

// Problem dims
#define L_   12
#define D_   1024
#define NH_  16
#define HD_  64
#define HID_ 2816
#define V_   50257
#define B_   8
#define T_   1024
#define M_   (B_*T_)        // 8192 tokens

// ---------------------------------------------------------------------------
// Scratch (static device globals — no allocations allowed)
// ---------------------------------------------------------------------------
__device__ float g_x  [M_ * D_];        // residual stream
__device__ float g_xf [B_ * D_];        // final-ln rows

__device__ __half g_ah[M_ * D_];        // LN / attention outputs (M x D)
__device__ __half g_al[M_ * D_];
__device__ __half g_uh[M_ * HID_];      // GLU output (M x HID) — disjoint
__device__ __half g_ul[M_ * HID_];

__device__ __half g_qh[M_ * D_];
__device__ __half g_ql[M_ * D_];
__device__ __half g_kh[M_ * D_];
__device__ __half g_kl[M_ * D_];
__device__ __half g_vh[M_ * D_];
__device__ __half g_vl[M_ * D_];

__device__ __half g_wch[L_ * 3 * D_ * D_];
__device__ __half g_wcl[L_ * 3 * D_ * D_];
__device__ __half g_wph[L_ * D_ * D_];
__device__ __half g_wpl[L_ * D_ * D_];
__device__ __half g_w1h[L_ * HID_ * D_];
__device__ __half g_w1l[L_ * HID_ * D_];
__device__ __half g_w3h[L_ * HID_ * D_];
__device__ __half g_w3l[L_ * HID_ * D_];
__device__ __half g_w2h[L_ * D_ * HID_];
__device__ __half g_w2l[L_ * D_ * HID_];

// ---------------------------------------------------------------------------
// Helpers
// ---------------------------------------------------------------------------
__device__ __forceinline__ uint32_t smem_u32(const void* p) {
    uint32_t a;
    asm("{ .reg .u64 t; cvta.to.shared.u64 t, %1; cvt.u32.u64 %0, t; }"
        : "=r"(a) : "l"(p));
    return a;
}

__device__ __forceinline__ uint32_t packh(float x, float y) {
    uint32_t r;
    asm("cvt.rn.f16x2.f32 %0, %1, %2;" : "=r"(r) : "f"(y), "f"(x));
    return r;
}

__device__ __forceinline__ float hf(float x) {
    return __half2float(__float2half_rn(x));
}

__device__ __forceinline__ void ldm_x4(uint32_t* r, uint32_t addr) {
    asm volatile("ldmatrix.sync.aligned.m8n8.x4.shared.b16 {%0,%1,%2,%3}, [%4];"
                 : "=r"(r[0]), "=r"(r[1]), "=r"(r[2]), "=r"(r[3]) : "r"(addr));
}
__device__ __forceinline__ void ldm_x4_t(uint32_t* r, uint32_t addr) {
    asm volatile("ldmatrix.sync.aligned.m8n8.x4.trans.shared.b16 {%0,%1,%2,%3}, [%4];"
                 : "=r"(r[0]), "=r"(r[1]), "=r"(r[2]), "=r"(r[3]) : "r"(addr));
}

__device__ __forceinline__ void mma16816(float* c, const uint32_t* a,
                                         const uint32_t* b) {
    asm volatile(
        "mma.sync.aligned.m16n8k16.row.col.f32.f16.f16.f32 "
        "{%0,%1,%2,%3}, {%4,%5,%6,%7}, {%8,%9}, {%0,%1,%2,%3};"
        : "+f"(c[0]), "+f"(c[1]), "+f"(c[2]), "+f"(c[3])
        : "r"(a[0]), "r"(a[1]), "r"(a[2]), "r"(a[3]), "r"(b[0]), "r"(b[1]));
}

__device__ __forceinline__ void cvt8(float4 f0, float4 f1, uint4& hi, uint4& lo) {
    float h0 = hf(f0.x), h1 = hf(f0.y), h2 = hf(f0.z), h3 = hf(f0.w);
    float h4 = hf(f1.x), h5 = hf(f1.y), h6 = hf(f1.z), h7 = hf(f1.w);
    hi.x = packh(h0, h1); hi.y = packh(h2, h3);
    hi.z = packh(h4, h5); hi.w = packh(h6, h7);
    lo.x = packh(f0.x - h0, f0.y - h1);
    lo.y = packh(f0.z - h2, f0.w - h3);
    lo.z = packh(f1.x - h4, f1.y - h5);
    lo.w = packh(f1.z - h6, f1.w - h7);
}

__device__ __forceinline__ void cpa16(uint32_t d, const void* s) {
    asm volatile("cp.async.cg.shared.global [%0], [%1], 16;" :: "r"(d), "l"(s));
}
__device__ __forceinline__ void cpcommit() {
    asm volatile("cp.async.commit_group;");
}
template <int N>
__device__ __forceinline__ void cpwait() {
    asm volatile("cp.async.wait_group %0;" :: "n"(N));
}

// ---------------------------------------------------------------------------
// Fused weight converter
// ---------------------------------------------------------------------------
#define WN0 4718592L
#define WN1 1572864L
#define WN2 4325376L
#define WTOT (WN0 + WN1 + 3 * WN2)

__global__ void wcvt_all_k(const float* __restrict__ cw, const float* __restrict__ pw,
                           const float* __restrict__ w1, const float* __restrict__ w3,
                           const float* __restrict__ w2,
                           __half* cwh, __half* cwl, __half* pwh, __half* pwl,
                           __half* w1h, __half* w1l, __half* w3h, __half* w3l,
                           __half* w2h, __half* w2l) {
    long i = (long)blockIdx.x * 256 + threadIdx.x;
    const float* src; __half* hi; __half* lo;
    if (i < WN0)              { src = cw; hi = cwh; lo = cwl; }
    else if ((i -= WN0) < WN1){ src = pw; hi = pwh; lo = pwl; }
    else if ((i -= WN1) < WN2){ src = w1; hi = w1h; lo = w1l; }
    else if ((i -= WN2) < WN2){ src = w3; hi = w3h; lo = w3l; }
    else { i -= WN2;            src = w2; hi = w2h; lo = w2l; }
    float4 f0 = ((const float4*)src)[i * 2];
    float4 f1 = ((const float4*)src)[i * 2 + 1];
    uint4 h, l;
    cvt8(f0, f1, h, l);
    ((uint4*)hi)[i] = h;
    ((uint4*)lo)[i] = l;
}

// ---------------------------------------------------------------------------
// GEMM mainloop — R11 structure. TERMS: 3 = full compensation (hh, lh, hl);
// 2 = drop W-lo term (a * bh), also skipping Wlo cp.async + LDSM.
// ---------------------------------------------------------------------------
#define RSTRIDE 80
#define STAGE_BYTES 40960

struct LoaderPtrs {
    const __half *pa0, *pal0, *pa1, *pal1;
    const __half *pw0, *pwl0, *pw1, *pwl1;
};

template <int TERMS>
__device__ __forceinline__ void gemm_mainloop(
    uint32_t sb, char* sm, int tid, int K, const LoaderPtrs& P,
    const uint32_t* arow, const uint32_t* brow, float acc[4][4][4]) {
    const int r0l = tid >> 2, c0l = tid & 3;
    const int r1l = (tid + 256) >> 2;

    auto load_stage = [&](int s, int kc) {
        uint32_t base = sb + (uint32_t)s * STAGE_BYTES;
        {
            uint32_t d = base + (uint32_t)(r0l * RSTRIDE + c0l * 16);
            cpa16(d +     0, P.pa0  + kc);
            cpa16(d + 10240, P.pal0 + kc);
            cpa16(d + 20480, P.pw0  + kc);
            if (TERMS >= 3) cpa16(d + 30720, P.pwl0 + kc);
        }
        {
            uint32_t d = base + (uint32_t)(r1l * RSTRIDE + c0l * 16);
            cpa16(d +     0, P.pa1  + kc);
            cpa16(d + 10240, P.pal1 + kc);
            cpa16(d + 20480, P.pw1  + kc);
            if (TERMS >= 3) cpa16(d + 30720, P.pwl1 + kc);
        }
    };

    const int nc = K >> 5;
    load_stage(0, 0);
    cpcommit();

    for (int j = 0; j < nc; j++) {
        cpwait<0>();
        __syncthreads();
        if (j + 1 < nc) {
            load_stage((j + 1) & 1, (j + 1) << 5);
            cpcommit();
        }

        const uint32_t base = sb + (uint32_t)(j & 1) * STAGE_BYTES;
        #pragma unroll
        for (int ks = 0; ks < 2; ks++) {
            const uint32_t ko = (uint32_t)(ks * 32);
            uint32_t bh[4][2], bl[4][2];
            #pragma unroll
            for (int p = 0; p < 2; p++) {
                uint32_t t4[4];
                ldm_x4(t4, base + 20480 + brow[p] + ko);
                bh[2*p][0] = t4[0]; bh[2*p][1] = t4[1];
                bh[2*p+1][0] = t4[2]; bh[2*p+1][1] = t4[3];
                if (TERMS >= 3) {
                    ldm_x4(t4, base + 30720 + brow[p] + ko);
                    bl[2*p][0] = t4[0]; bl[2*p][1] = t4[1];
                    bl[2*p+1][0] = t4[2]; bl[2*p+1][1] = t4[3];
                }
            }
            uint32_t ahb[2][4], alb[2][4];
            ldm_x4(ahb[0], base +     0 + arow[0] + ko);
            ldm_x4(alb[0], base + 10240 + arow[0] + ko);
            #pragma unroll
            for (int mt = 0; mt < 4; mt++) {
                const int cur = mt & 1;
                if (mt < 3) {
                    ldm_x4(ahb[cur ^ 1], base +     0 + arow[mt + 1] + ko);
                    ldm_x4(alb[cur ^ 1], base + 10240 + arow[mt + 1] + ko);
                }
                #pragma unroll
                for (int nt = 0; nt < 4; nt++)
                    mma16816(acc[mt][nt], ahb[cur], bh[nt]);
                #pragma unroll
                for (int nt = 0; nt < 4; nt++)
                    mma16816(acc[mt][nt], alb[cur], bh[nt]);
                if (TERMS >= 3) {
                    #pragma unroll
                    for (int nt = 0; nt < 4; nt++)
                        mma16816(acc[mt][nt], ahb[cur], bl[nt]);
                }
            }
        }
    }
    __syncthreads();
}

#define GEMM_PROLOG                                                            \
    extern __shared__ __align__(16) char sm[];                                 \
    const uint32_t sb = smem_u32(sm);                                          \
    const int tid = threadIdx.x;                                               \
    const int warp = tid >> 5, lane = tid & 31;                                \
    const int wm = warp & 1, wn = warp >> 1;                                   \
    const int gid = lane >> 2, tg = lane & 3;                                  \
    const int l15 = lane & 15, l16 = (lane >> 4) & 1;                          \
    const int l7 = lane & 7, l8 = (lane >> 3) & 1;                             \
    uint32_t arow[4], brow[2];                                                 \
    _Pragma("unroll")                                                          \
    for (int mt = 0; mt < 4; mt++)                                             \
        arow[mt] = (uint32_t)((wm * 64 + mt * 16 + l15) * RSTRIDE + l16 * 16); \
    _Pragma("unroll")                                                          \
    for (int p = 0; p < 2; p++)                                                \
        brow[p] = (uint32_t)((wn * 32 + p * 16 + l7 + l16 * 8) * RSTRIDE + l8 * 16); \
    float acc[4][4][4];                                                        \
    _Pragma("unroll")                                                          \
    for (int i = 0; i < 4; i++)                                                \
        _Pragma("unroll")                                                      \
        for (int j = 0; j < 4; j++)                                            \
            _Pragma("unroll")                                                  \
            for (int c = 0; c < 4; c++) acc[i][j][c] = 0.f;                    \
    const int r0l = tid >> 2, c0l = tid & 3;                                   \
    const int r1l = (tid + 256) >> 2;

// ---------------------------------------------------------------------------
// Standard GEMM "NT" (proj / w2): C = A@W^T (+bias)(+residual). TERMS templ.
// ---------------------------------------------------------------------------
template <int TERMS>
__global__ void __launch_bounds__(256, 2)
hgemm16(const __half* __restrict__ a_hi, const __half* __restrict__ a_lo,
        const __half* __restrict__ w_hi, const __half* __restrict__ w_lo,
        const float* __restrict__ bias, float* __restrict__ C,
        int M, int N, int K, int residual) {
    GEMM_PROLOG
    const int by = blockIdx.y * 128, bx = blockIdx.x * 128;
    LoaderPtrs P;
    P.pa0  = a_hi + (size_t)(by + r0l) * K + c0l * 8;
    P.pal0 = a_lo + (size_t)(by + r0l) * K + c0l * 8;
    P.pa1  = a_hi + (size_t)(by + r1l) * K + c0l * 8;
    P.pal1 = a_lo + (size_t)(by + r1l) * K + c0l * 8;
    P.pw0  = w_hi + (size_t)(bx + r0l) * K + c0l * 8;
    P.pwl0 = w_lo + (size_t)(bx + r0l) * K + c0l * 8;
    P.pw1  = w_hi + (size_t)(bx + r1l) * K + c0l * 8;
    P.pwl1 = w_lo + (size_t)(bx + r1l) * K + c0l * 8;
    gemm_mainloop<TERMS>(sb, sm, tid, K, P, arow, brow, acc);

    const size_t mBase = (size_t)by + wm * 64;
    const int    nBase = bx + wn * 32;
    #pragma unroll
    for (int mt = 0; mt < 4; mt++) {
        #pragma unroll
        for (int nt = 0; nt < 4; nt++) {
            int c0 = nBase + nt * 8 + tg * 2;
            float b0 = bias ? bias[c0]     : 0.f;
            float b1 = bias ? bias[c0 + 1] : 0.f;
            size_t r0 = mBase + mt * 16 + gid;
            float* p0 = C + r0 * N + c0;
            float* p1 = C + (r0 + 8) * N + c0;
            float v00 = acc[mt][nt][0] + b0, v01 = acc[mt][nt][1] + b1;
            float v10 = acc[mt][nt][2] + b0, v11 = acc[mt][nt][3] + b1;
            if (residual) { v00 += p0[0]; v01 += p0[1]; v10 += p1[0]; v11 += p1[1]; }
            p0[0] = v00; p0[1] = v01;
            p1[0] = v10; p1[1] = v11;
        }
    }
}

// ---------------------------------------------------------------------------
// QKV GEMM with fused bias + RoPE + fp16 hi/lo split output. 3-term.
// ---------------------------------------------------------------------------
__global__ void __launch_bounds__(256, 2)
hgemm16_qkv(const __half* __restrict__ a_hi, const __half* __restrict__ a_lo,
            const __half* __restrict__ w_hi, const __half* __restrict__ w_lo,
            const float* __restrict__ bias,
            __half* __restrict__ qh, __half* __restrict__ ql,
            __half* __restrict__ kh, __half* __restrict__ kl,
            __half* __restrict__ vh, __half* __restrict__ vl) {
    GEMM_PROLOG
    const int K = D_;
    const int by = blockIdx.y * 128, bx = blockIdx.x * 128;
    LoaderPtrs P;
    P.pa0  = a_hi + (size_t)(by + r0l) * K + c0l * 8;
    P.pal0 = a_lo + (size_t)(by + r0l) * K + c0l * 8;
    P.pa1  = a_hi + (size_t)(by + r1l) * K + c0l * 8;
    P.pal1 = a_lo + (size_t)(by + r1l) * K + c0l * 8;
    P.pw0  = w_hi + (size_t)(bx + r0l) * K + c0l * 8;
    P.pwl0 = w_lo + (size_t)(bx + r0l) * K + c0l * 8;
    P.pw1  = w_hi + (size_t)(bx + r1l) * K + c0l * 8;
    P.pwl1 = w_lo + (size_t)(bx + r1l) * K + c0l * 8;
    gemm_mainloop<3>(sb, sm, tid, K, P, arow, brow, acc);

    // stage fp32 tile (+bias) in smem: [128][132]
    float* smf = (float*)sm;
    #pragma unroll
    for (int mt = 0; mt < 4; mt++) {
        #pragma unroll
        for (int nt = 0; nt < 4; nt++) {
            int col = wn * 32 + nt * 8 + tg * 2;
            int row = wm * 64 + mt * 16 + gid;
            float b0 = bias[bx + col], b1 = bias[bx + col + 1];
            smf[row * 132 + col]           = acc[mt][nt][0] + b0;
            smf[row * 132 + col + 1]       = acc[mt][nt][1] + b1;
            smf[(row + 8) * 132 + col]     = acc[mt][nt][2] + b0;
            smf[(row + 8) * 132 + col + 1] = acc[mt][nt][3] + b1;
        }
    }
    __syncthreads();

    const int region = blockIdx.x >> 3;      // 0 q, 1 k, 2 v
    #pragma unroll 4
    for (int it = 0; it < 16; it++) {
        int idx = tid + it * 256;            // 4096 quads
        int r = idx >> 5;
        int c4 = (idx & 31) * 4;
        int mrow = by + r;
        float4 x4 = *(float4*)&smf[r * 132 + c4];
        float o0, o1, o2, o3;
        __half *dh, *dl;
        int dcol;
        if (region < 2) {
            int cg = bx + c4;
            int hc = cg & 63;
            int hi_half = hc & 32;
            float4 p4 = *(float4*)&smf[r * 132 + (hi_half ? c4 - 32 : c4 + 32)];
            int t = mrow & (T_ - 1);
            float oo[4];
            float xv[4] = {x4.x, x4.y, x4.z, x4.w};
            float pv[4] = {p4.x, p4.y, p4.z, p4.w};
            #pragma unroll
            for (int e = 0; e < 4; e++) {
                int i = (hc & 31) + e;
                float inv = exp2f((float)i * (-13.28771237954945f / 32.0f));
                float ang = (float)t * inv;
                float sn, cs;
                sincosf(ang, &sn, &cs);
                oo[e] = hi_half ? (xv[e] * cs + pv[e] * sn)
                                : (xv[e] * cs - pv[e] * sn);
            }
            if (region == 0) {
                o0 = oo[0] * 0.125f; o1 = oo[1] * 0.125f;
                o2 = oo[2] * 0.125f; o3 = oo[3] * 0.125f;
                dh = qh; dl = ql; dcol = cg;
            } else {
                o0 = oo[0]; o1 = oo[1]; o2 = oo[2]; o3 = oo[3];
                dh = kh; dl = kl; dcol = cg - D_;
            }
        } else {
            o0 = x4.x; o1 = x4.y; o2 = x4.z; o3 = x4.w;
            dh = vh; dl = vl; dcol = bx + c4 - 2 * D_;
        }
        float h0 = hf(o0), h1 = hf(o1), h2 = hf(o2), h3 = hf(o3);
        uint2 hh, ll;
        hh.x = packh(h0, h1); hh.y = packh(h2, h3);
        ll.x = packh(o0 - h0, o1 - h1); ll.y = packh(o2 - h2, o3 - h3);
        *(uint2*)(dh + (size_t)mrow * D_ + dcol) = hh;
        *(uint2*)(dl + (size_t)mrow * D_ + dcol) = ll;
    }
}

// ---------------------------------------------------------------------------
// Fused GLU GEMM — 2-TERM compensation (a*bh): u = A@w1h^T, g = A@w3h^T,
// out = silu(u)*g as fp16 hi/lo. Outputs disjoint from inputs.
// ---------------------------------------------------------------------------
__global__ void __launch_bounds__(256, 2)
hgemm16_glu(const __half* __restrict__ a_hi, const __half* __restrict__ a_lo,
            const __half* __restrict__ w1h, const __half* __restrict__ w1l,
            const __half* __restrict__ w3h, const __half* __restrict__ w3l,
            __half* __restrict__ oh, __half* __restrict__ ol) {
    GEMM_PROLOG
    const int K = D_;
    const int by = blockIdx.y * 128;
    const int bx64 = blockIdx.x * 64;
    LoaderPtrs P;
    P.pa0  = a_hi + (size_t)(by + r0l) * K + c0l * 8;
    P.pal0 = a_lo + (size_t)(by + r0l) * K + c0l * 8;
    P.pa1  = a_hi + (size_t)(by + r1l) * K + c0l * 8;
    P.pal1 = a_lo + (size_t)(by + r1l) * K + c0l * 8;
    P.pw0  = w1h + (size_t)(bx64 + r0l) * K + c0l * 8;
    P.pwl0 = w1l + (size_t)(bx64 + r0l) * K + c0l * 8;
    P.pw1  = w3h + (size_t)(bx64 + r0l) * K + c0l * 8;
    P.pwl1 = w3l + (size_t)(bx64 + r0l) * K + c0l * 8;
    gemm_mainloop<2>(sb, sm, tid, K, P, arow, brow, acc);

    // stage fp32 [128][132]: cols 0..63 = u, 64..127 = g
    float* smf = (float*)sm;
    #pragma unroll
    for (int mt = 0; mt < 4; mt++) {
        #pragma unroll
        for (int nt = 0; nt < 4; nt++) {
            int col = wn * 32 + nt * 8 + tg * 2;
            int row = wm * 64 + mt * 16 + gid;
            smf[row * 132 + col]           = acc[mt][nt][0];
            smf[row * 132 + col + 1]       = acc[mt][nt][1];
            smf[(row + 8) * 132 + col]     = acc[mt][nt][2];
            smf[(row + 8) * 132 + col + 1] = acc[mt][nt][3];
        }
    }
    __syncthreads();

    #pragma unroll 4
    for (int it = 0; it < 8; it++) {
        int idx = tid + it * 256;            // 2048 quads (128 x 64 / 4)
        int r = idx >> 4;
        int c4 = (idx & 15) * 4;
        float4 uv = *(float4*)&smf[r * 132 + c4];
        float4 gv = *(float4*)&smf[r * 132 + c4 + 64];
        float o0 = uv.x / (1.f + expf(-uv.x)) * gv.x;
        float o1 = uv.y / (1.f + expf(-uv.y)) * gv.y;
        float o2 = uv.z / (1.f + expf(-uv.z)) * gv.z;
        float o3 = uv.w / (1.f + expf(-uv.w)) * gv.w;
        float h0 = hf(o0), h1 = hf(o1), h2 = hf(o2), h3 = hf(o3);
        uint2 hh, ll;
        hh.x = packh(h0, h1); hh.y = packh(h2, h3);
        ll.x = packh(o0 - h0, o1 - h1); ll.y = packh(o2 - h2, o3 - h3);
        size_t off = (size_t)(by + r) * HID_ + bx64 + c4;
        *(uint2*)(oh + off) = hh;
        *(uint2*)(ol + off) = ll;
    }
}

// ---------------------------------------------------------------------------
// Embedding gather
// ---------------------------------------------------------------------------
__global__ void embed_k(const int* __restrict__ tok, const float* __restrict__ wte,
                        float* __restrict__ x) {
    int m = blockIdx.x;
    int t = tok[m];
    const float4* src = (const float4*)(wte + (size_t)t * D_);
    float4* dst = (float4*)(x + (size_t)m * D_);
    dst[threadIdx.x] = src[threadIdx.x];
}

// ---------------------------------------------------------------------------
// LayerNorm cores
// ---------------------------------------------------------------------------
__device__ __forceinline__ void ln_core(const float* xr, int tid,
                                        float4& v, float& mean, float& rstd) {
    v = ((const float4*)xr)[tid];
    float s = v.x + v.y + v.z + v.w;
    float q = v.x*v.x + v.y*v.y + v.z*v.z + v.w*v.w;
    #pragma unroll
    for (int off = 16; off > 0; off >>= 1) {
        s += __shfl_down_sync(0xffffffffu, s, off);
        q += __shfl_down_sync(0xffffffffu, q, off);
    }
    __shared__ float ss[8], sq[8];
    int wi = tid >> 5, ln = tid & 31;
    if (ln == 0) { ss[wi] = s; sq[wi] = q; }
    __syncthreads();
    if (tid == 0) {
        float a = 0.f, c = 0.f;
        #pragma unroll
        for (int i = 0; i < 8; i++) { a += ss[i]; c += sq[i]; }
        ss[0] = a; sq[0] = c;
    }
    __syncthreads();
    mean = ss[0] * (1.f / D_);
    float var = sq[0] * (1.f / D_) - mean * mean;
    rstd = rsqrtf(var + 1e-5f);
}

__global__ void ln_k(const float* __restrict__ x, const float* __restrict__ w,
                     const float* __restrict__ b, float* __restrict__ o,
                     int rowStride) {
    int row = blockIdx.x, tid = threadIdx.x;
    float4 v; float mean, rstd;
    ln_core(x + (size_t)row * rowStride, tid, v, mean, rstd);
    float4 wv = ((const float4*)w)[tid];
    float4 bv = ((const float4*)b)[tid];
    float4 ov;
    ov.x = (v.x - mean) * rstd * wv.x + bv.x;
    ov.y = (v.y - mean) * rstd * wv.y + bv.y;
    ov.z = (v.z - mean) * rstd * wv.z + bv.z;
    ov.w = (v.w - mean) * rstd * wv.w + bv.w;
    ((float4*)(o + (size_t)row * D_))[tid] = ov;
}

__global__ void ln_cvt_k(const float* __restrict__ x, const float* __restrict__ w,
                         const float* __restrict__ b, __half* __restrict__ hi,
                         __half* __restrict__ lo) {
    int row = blockIdx.x, tid = threadIdx.x;
    float4 v; float mean, rstd;
    ln_core(x + (size_t)row * D_, tid, v, mean, rstd);
    float4 wv = ((const float4*)w)[tid];
    float4 bv = ((const float4*)b)[tid];
    float o0 = (v.x - mean) * rstd * wv.x + bv.x;
    float o1 = (v.y - mean) * rstd * wv.y + bv.y;
    float o2 = (v.z - mean) * rstd * wv.z + bv.z;
    float o3 = (v.w - mean) * rstd * wv.w + bv.w;
    size_t ob = (size_t)row * D_ + tid * 4;
    float h0 = hf(o0), h1 = hf(o1), h2 = hf(o2), h3 = hf(o3);
    uint2 hh, ll;
    hh.x = packh(h0, h1); hh.y = packh(h2, h3);
    ll.x = packh(o0 - h0, o1 - h1); ll.y = packh(o2 - h2, o3 - h3);
    *(uint2*)(hi + ob) = hh;
    *(uint2*)(lo + ob) = ll;
}

// ---------------------------------------------------------------------------
// MMA flash attention (proven R7 kernel, unchanged)
// ---------------------------------------------------------------------------
#define ARS 72
#define ATT_SMEM 92160

__global__ void __launch_bounds__(128)
mma_attn(const __half* __restrict__ qh, const __half* __restrict__ ql,
         const __half* __restrict__ kh, const __half* __restrict__ kl,
         const __half* __restrict__ vh, const __half* __restrict__ vl,
         __half* __restrict__ oh, __half* __restrict__ ol) {
    extern __shared__ __align__(16) __half sa[];
    const int qt = blockIdx.x, h = blockIdx.y, b = blockIdx.z;
    const int q0 = qt * 64;
    const int tid = threadIdx.x, w = tid >> 5, lane = tid & 31;
    const int gid = lane >> 2, tg = lane & 3;
    const int l7 = lane & 7, l8 = (lane >> 3) & 1, l16 = (lane >> 4) & 1;
    const uint32_t sb = smem_u32(sa);

    const int QHI = 0, QLO = 4608, STG = 9216, STGSZ = 18432;

    for (int i = tid; i < 1024; i += 128) {
        int arr = i >> 9, rem = i & 511, row = rem >> 3, ch = rem & 7;
        const __half* src = (arr ? ql : qh) +
            (size_t)(b * T_ + q0 + row) * D_ + h * 64 + ch * 8;
        *(uint4*)(sa + (arr ? QLO : QHI) + row * ARS + ch * 8) = *(const uint4*)src;
    }

    auto load_kv = [&](int s, int kt) {
        const __half* srcs[4] = {kh, kl, vh, vl};
        int base0 = STG + s * STGSZ;
        for (int i = tid; i < 2048; i += 128) {
            int arr = i >> 9, rem = i & 511, row = rem >> 3, ch = rem & 7;
            const __half* src = srcs[arr] +
                (size_t)(b * T_ + kt * 64 + row) * D_ + h * 64 + ch * 8;
            uint32_t dst = sb + (uint32_t)(base0 + arr * 4608 + row * ARS + ch * 8) * 2;
            cpa16(dst, src);
        }
    };

    load_kv(0, 0);
    cpcommit();
    __syncthreads();

    uint32_t aqh[4][4], aql[4][4];
    {
        uint32_t abase = sb + (uint32_t)((w * 16 + (lane & 15)) * ARS + l16 * 8) * 2;
        #pragma unroll
        for (int kc = 0; kc < 4; kc++) {
            ldm_x4(aqh[kc], abase + kc * 32);
            ldm_x4(aql[kc], abase + 9216 + kc * 32);
        }
    }

    float m0 = -1e30f, m1 = -1e30f, l0 = 0.f, l1 = 0.f;
    float O[8][4];
    #pragma unroll
    for (int n = 0; n < 8; n++)
        #pragma unroll
        for (int c = 0; c < 4; c++) O[n][c] = 0.f;

    const int nt = qt + 1;
    for (int kt = 0; kt < nt; kt++) {
        const int s = kt & 1;
        if (kt + 1 < nt) { load_kv(s ^ 1, kt + 1); cpcommit(); cpwait<1>(); }
        else             { cpwait<0>(); }
        __syncthreads();

        const uint32_t kbase = sb + (uint32_t)(STG + s * STGSZ) * 2;

        float S[8][4];
        #pragma unroll
        for (int n = 0; n < 8; n++)
            #pragma unroll
            for (int c = 0; c < 4; c++) S[n][c] = 0.f;

        #pragma unroll
        for (int kc = 0; kc < 4; kc++) {
            #pragma unroll
            for (int np = 0; np < 4; np++) {
                uint32_t addr = kbase +
                    (uint32_t)((np * 16 + l7 + l16 * 8) * ARS) * 2 + l8 * 16 + kc * 32;
                uint32_t bh4[4], bl4[4];
                ldm_x4(bh4, addr);
                ldm_x4(bl4, addr + 9216);
                mma16816(S[2*np],   aqh[kc], bh4 + 0);
                mma16816(S[2*np],   aql[kc], bh4 + 0);
                mma16816(S[2*np],   aqh[kc], bl4 + 0);
                mma16816(S[2*np+1], aqh[kc], bh4 + 2);
                mma16816(S[2*np+1], aql[kc], bh4 + 2);
                mma16816(S[2*np+1], aqh[kc], bl4 + 2);
            }
        }

        if (kt == qt) {
            #pragma unroll
            for (int n = 0; n < 8; n++)
                #pragma unroll
                for (int c = 0; c < 4; c++) {
                    int qg = w * 16 + gid + (c >> 1) * 8;
                    int kg = n * 8 + 2 * tg + (c & 1);
                    if (kg > qg) S[n][c] = -1e30f;
                }
        }

        float mt0 = -1e30f, mt1 = -1e30f;
        #pragma unroll
        for (int n = 0; n < 8; n++) {
            mt0 = fmaxf(mt0, fmaxf(S[n][0], S[n][1]));
            mt1 = fmaxf(mt1, fmaxf(S[n][2], S[n][3]));
        }
        mt0 = fmaxf(mt0, __shfl_xor_sync(0xffffffffu, mt0, 1));
        mt0 = fmaxf(mt0, __shfl_xor_sync(0xffffffffu, mt0, 2));
        mt1 = fmaxf(mt1, __shfl_xor_sync(0xffffffffu, mt1, 1));
        mt1 = fmaxf(mt1, __shfl_xor_sync(0xffffffffu, mt1, 2));
        float mn0 = fmaxf(m0, mt0), mn1 = fmaxf(m1, mt1);
        float a0 = expf(m0 - mn0), a1 = expf(m1 - mn1);
        float ps0 = 0.f, ps1 = 0.f;
        #pragma unroll
        for (int n = 0; n < 8; n++) {
            S[n][0] = expf(S[n][0] - mn0); ps0 += S[n][0];
            S[n][1] = expf(S[n][1] - mn0); ps0 += S[n][1];
            S[n][2] = expf(S[n][2] - mn1); ps1 += S[n][2];
            S[n][3] = expf(S[n][3] - mn1); ps1 += S[n][3];
        }
        ps0 += __shfl_xor_sync(0xffffffffu, ps0, 1);
        ps0 += __shfl_xor_sync(0xffffffffu, ps0, 2);
        ps1 += __shfl_xor_sync(0xffffffffu, ps1, 1);
        ps1 += __shfl_xor_sync(0xffffffffu, ps1, 2);
        l0 = l0 * a0 + ps0; l1 = l1 * a1 + ps1;
        m0 = mn0; m1 = mn1;
        #pragma unroll
        for (int n = 0; n < 8; n++) {
            O[n][0] *= a0; O[n][1] *= a0;
            O[n][2] *= a1; O[n][3] *= a1;
        }

        const uint32_t vbase = kbase + 18432;
        #pragma unroll
        for (int kc = 0; kc < 4; kc++) {
            float p0 = S[2*kc][0],   p1 = S[2*kc][1];
            float p2 = S[2*kc][2],   p3 = S[2*kc][3];
            float r0 = S[2*kc+1][0], r1 = S[2*kc+1][1];
            float r2 = S[2*kc+1][2], r3 = S[2*kc+1][3];
            float hp0 = hf(p0), hp1 = hf(p1), hp2 = hf(p2), hp3 = hf(p3);
            float hr0 = hf(r0), hr1 = hf(r1), hr2 = hf(r2), hr3 = hf(r3);
            uint32_t pah[4], pal[4];
            pah[0] = packh(hp0, hp1); pah[1] = packh(hp2, hp3);
            pah[2] = packh(hr0, hr1); pah[3] = packh(hr2, hr3);
            pal[0] = packh(p0 - hp0, p1 - hp1); pal[1] = packh(p2 - hp2, p3 - hp3);
            pal[2] = packh(r0 - hr0, r1 - hr1); pal[3] = packh(r2 - hr2, r3 - hr3);
            #pragma unroll
            for (int ndp = 0; ndp < 4; ndp++) {
                uint32_t addr = vbase +
                    (uint32_t)((kc * 16 + l7 + l8 * 8) * ARS) * 2 + ndp * 32 + l16 * 16;
                uint32_t bh4[4], bl4[4];
                ldm_x4_t(bh4, addr);
                ldm_x4_t(bl4, addr + 9216);
                mma16816(O[2*ndp],   pah, bh4 + 0);
                mma16816(O[2*ndp],   pal, bh4 + 0);
                mma16816(O[2*ndp],   pah, bl4 + 0);
                mma16816(O[2*ndp+1], pah, bh4 + 2);
                mma16816(O[2*ndp+1], pal, bh4 + 2);
                mma16816(O[2*ndp+1], pah, bl4 + 2);
            }
        }
        __syncthreads();
    }

    float i0 = 1.f / l0, i1 = 1.f / l1;
    size_t mrow0 = (size_t)(b * T_ + q0 + w * 16 + gid);
    #pragma unroll
    for (int nd = 0; nd < 8; nd++) {
        int col = h * 64 + nd * 8 + 2 * tg;
        float v0 = O[nd][0] * i0, v1 = O[nd][1] * i0;
        float v2 = O[nd][2] * i1, v3 = O[nd][3] * i1;
        float h0 = hf(v0), h1 = hf(v1), h2 = hf(v2), h3 = hf(v3);
        *(uint32_t*)(oh + mrow0 * D_ + col)       = packh(h0, h1);
        *(uint32_t*)(ol + mrow0 * D_ + col)       = packh(v0 - h0, v1 - h1);
        *(uint32_t*)(oh + (mrow0 + 8) * D_ + col) = packh(h2, h3);
        *(uint32_t*)(ol + (mrow0 + 8) * D_ + col) = packh(v2 - h2, v3 - h3);
    }
}

// ---------------------------------------------------------------------------
// Logits
// ---------------------------------------------------------------------------
__global__ void __launch_bounds__(256)
logits_k(const float* __restrict__ xf, const float* __restrict__ wte,
         float* __restrict__ out) {
    __shared__ float xs[B_ * D_];
    int tid = threadIdx.x;
    #pragma unroll
    for (int p = 0; p < 8; p++) {
        int i4 = tid + p * 256;
        float4 v = ((const float4*)xf)[i4];
        xs[i4 * 4 + 0] = v.x; xs[i4 * 4 + 1] = v.y;
        xs[i4 * 4 + 2] = v.z; xs[i4 * 4 + 3] = v.w;
    }
    __syncthreads();
    int n = blockIdx.x * 256 + tid;
    if (n >= V_) return;
    const float* wr = wte + (size_t)n * D_;
    float acc[8] = {0.f, 0.f, 0.f, 0.f, 0.f, 0.f, 0.f, 0.f};
    for (int k = 0; k < D_; k += 4) {
        float4 w = *(const float4*)(wr + k);
        #pragma unroll
        for (int b2 = 0; b2 < 8; b2++) {
            const float* xb = xs + b2 * D_ + k;
            acc[b2] += w.x * xb[0] + w.y * xb[1] + w.z * xb[2] + w.w * xb[3];
        }
    }
    #pragma unroll
    for (int b2 = 0; b2 < 8; b2++) out[(size_t)b2 * V_ + n] = acc[b2];
}

// ---------------------------------------------------------------------------
// Host orchestration
// ---------------------------------------------------------------------------
extern "C" void kernel_launch(void* const* d_in, const int* in_sizes, int n_in,
                              void* d_out, int out_size) {
    const int*   tokens   = (const int*)  d_in[0];
    const float* wte      = (const float*)d_in[1];
    const float* c_attn_w = (const float*)d_in[2];
    const float* c_attn_b = (const float*)d_in[3];
    const float* c_proj_w = (const float*)d_in[4];
    const float* c_proj_b = (const float*)d_in[5];
    const float* ln1_w    = (const float*)d_in[6];
    const float* ln1_b    = (const float*)d_in[7];
    const float* ln2_w    = (const float*)d_in[8];
    const float* ln2_b    = (const float*)d_in[9];
    const float* w1       = (const float*)d_in[10];
    const float* w3       = (const float*)d_in[11];
    const float* w2       = (const float*)d_in[12];
    const float* lnf_w    = (const float*)d_in[13];
    const float* lnf_b    = (const float*)d_in[14];
    float* out = (float*)d_out;

    float *x, *xf;
    cudaGetSymbolAddress((void**)&x,  g_x);
    cudaGetSymbolAddress((void**)&xf, g_xf);

    __half *ah, *al, *uh, *ul, *qh, *ql, *kh, *kl, *vh, *vl;
    cudaGetSymbolAddress((void**)&ah, g_ah);
    cudaGetSymbolAddress((void**)&al, g_al);
    cudaGetSymbolAddress((void**)&uh, g_uh);
    cudaGetSymbolAddress((void**)&ul, g_ul);
    cudaGetSymbolAddress((void**)&qh, g_qh);
    cudaGetSymbolAddress((void**)&ql, g_ql);
    cudaGetSymbolAddress((void**)&kh, g_kh);
    cudaGetSymbolAddress((void**)&kl, g_kl);
    cudaGetSymbolAddress((void**)&vh, g_vh);
    cudaGetSymbolAddress((void**)&vl, g_vl);

    __half *wch, *wcl, *wph, *wpl, *w1h, *w1l, *w3h, *w3l, *w2h, *w2l;
    cudaGetSymbolAddress((void**)&wch, g_wch);
    cudaGetSymbolAddress((void**)&wcl, g_wcl);
    cudaGetSymbolAddress((void**)&wph, g_wph);
    cudaGetSymbolAddress((void**)&wpl, g_wpl);
    cudaGetSymbolAddress((void**)&w1h, g_w1h);
    cudaGetSymbolAddress((void**)&w1l, g_w1l);
    cudaGetSymbolAddress((void**)&w3h, g_w3h);
    cudaGetSymbolAddress((void**)&w3l, g_w3l);
    cudaGetSymbolAddress((void**)&w2h, g_w2h);
    cudaGetSymbolAddress((void**)&w2l, g_w2l);

    const int SMEM = 2 * STAGE_BYTES;
    cudaFuncSetAttribute(hgemm16<3>, cudaFuncAttributeMaxDynamicSharedMemorySize, SMEM);
    cudaFuncSetAttribute(hgemm16<2>, cudaFuncAttributeMaxDynamicSharedMemorySize, SMEM);
    cudaFuncSetAttribute(hgemm16_qkv, cudaFuncAttributeMaxDynamicSharedMemorySize, SMEM);
    cudaFuncSetAttribute(hgemm16_glu, cudaFuncAttributeMaxDynamicSharedMemorySize, SMEM);
    cudaFuncSetAttribute(mma_attn, cudaFuncAttributeMaxDynamicSharedMemorySize, ATT_SMEM);

    wcvt_all_k<<<(int)(WTOT / 256), 256>>>(
        c_attn_w, c_proj_w, w1, w3, w2,
        wch, wcl, wph, wpl, w1h, w1l, w3h, w3l, w2h, w2l);

    embed_k<<<M_, 256>>>(tokens, wte, x);

    for (int l = 0; l < L_; l++) {
        ln_cvt_k<<<M_, 256>>>(x, ln1_w + l * D_, ln1_b + l * D_, ah, al);
        hgemm16_qkv<<<dim3(3 * D_ / 128, M_ / 128), 256, SMEM>>>(
            ah, al, wch + (size_t)l * 3 * D_ * D_, wcl + (size_t)l * 3 * D_ * D_,
            c_attn_b + l * 3 * D_, qh, ql, kh, kl, vh, vl);
        mma_attn<<<dim3(T_ / 64, NH_, B_), 128, ATT_SMEM>>>(
            qh, ql, kh, kl, vh, vl, ah, al);
        // proj: 2-term (drop W-lo)
        hgemm16<2><<<dim3(D_ / 128, M_ / 128), 256, SMEM>>>(
            ah, al, wph + (size_t)l * D_ * D_, wpl + (size_t)l * D_ * D_,
            c_proj_b + l * D_, x, M_, D_, D_, 1);
        ln_cvt_k<<<M_, 256>>>(x, ln2_w + l * D_, ln2_b + l * D_, ah, al);
        hgemm16_glu<<<dim3(HID_ / 64, M_ / 128), 256, SMEM>>>(
            ah, al, w1h + (size_t)l * HID_ * D_, w1l + (size_t)l * HID_ * D_,
            w3h + (size_t)l * HID_ * D_, w3l + (size_t)l * HID_ * D_, uh, ul);
        // w2: 2-term (drop W-lo)
        hgemm16<2><<<dim3(D_ / 128, M_ / 128), 256, SMEM>>>(
            uh, ul, w2h + (size_t)l * D_ * HID_, w2l + (size_t)l * D_ * HID_,
            nullptr, x, M_, D_, HID_, 1);
    }

    ln_k<<<B_, 256>>>(x + (size_t)(T_ - 1) * D_, lnf_w, lnf_b, xf, T_ * D_);
    logits_k<<<(V_ + 255) / 256, 256>>>(xf, wte, out);
}

// round 16
// speedup vs baseline: 1.7840x; 1.0470x over previous
#include <cuda_runtime.h>
#include <cuda_fp16.h>
#include <math.h>
#include <stdint.h>

// Problem dims
#define L_   12
#define D_   1024
#define NH_  16
#define HD_  64
#define HID_ 2816
#define V_   50257
#define B_   8
#define T_   1024
#define M_   (B_*T_)        // 8192 tokens

// ---------------------------------------------------------------------------
// Scratch (static device globals — no allocations allowed)
// ---------------------------------------------------------------------------
__device__ float g_x  [M_ * D_];        // residual stream
__device__ float g_xf [B_ * D_];        // final-ln rows

__device__ __half g_ah[M_ * D_];
__device__ __half g_al[M_ * D_];
__device__ __half g_uh[M_ * HID_];
__device__ __half g_ul[M_ * HID_];

__device__ __half g_qh[M_ * D_];
__device__ __half g_ql[M_ * D_];
__device__ __half g_kh[M_ * D_];
__device__ __half g_kl[M_ * D_];
__device__ __half g_vh[M_ * D_];
__device__ __half g_vl[M_ * D_];

__device__ __half g_wch[L_ * 3 * D_ * D_];
__device__ __half g_wcl[L_ * 3 * D_ * D_];
__device__ __half g_wph[L_ * D_ * D_];
__device__ __half g_wpl[L_ * D_ * D_];
__device__ __half g_w1h[L_ * HID_ * D_];
__device__ __half g_w1l[L_ * HID_ * D_];
__device__ __half g_w3h[L_ * HID_ * D_];
__device__ __half g_w3l[L_ * HID_ * D_];
__device__ __half g_w2h[L_ * D_ * HID_];
__device__ __half g_w2l[L_ * D_ * HID_];

// ---------------------------------------------------------------------------
// Helpers
// ---------------------------------------------------------------------------
__device__ __forceinline__ uint32_t smem_u32(const void* p) {
    uint32_t a;
    asm("{ .reg .u64 t; cvta.to.shared.u64 t, %1; cvt.u32.u64 %0, t; }"
        : "=r"(a) : "l"(p));
    return a;
}

__device__ __forceinline__ uint32_t packh(float x, float y) {
    uint32_t r;
    asm("cvt.rn.f16x2.f32 %0, %1, %2;" : "=r"(r) : "f"(y), "f"(x));
    return r;
}

__device__ __forceinline__ float hf(float x) {
    return __half2float(__float2half_rn(x));
}

__device__ __forceinline__ void ldm_x4(uint32_t* r, uint32_t addr) {
    asm volatile("ldmatrix.sync.aligned.m8n8.x4.shared.b16 {%0,%1,%2,%3}, [%4];"
                 : "=r"(r[0]), "=r"(r[1]), "=r"(r[2]), "=r"(r[3]) : "r"(addr));
}
__device__ __forceinline__ void ldm_x4_t(uint32_t* r, uint32_t addr) {
    asm volatile("ldmatrix.sync.aligned.m8n8.x4.trans.shared.b16 {%0,%1,%2,%3}, [%4];"
                 : "=r"(r[0]), "=r"(r[1]), "=r"(r[2]), "=r"(r[3]) : "r"(addr));
}

__device__ __forceinline__ void mma16816(float* c, const uint32_t* a,
                                         const uint32_t* b) {
    asm volatile(
        "mma.sync.aligned.m16n8k16.row.col.f32.f16.f16.f32 "
        "{%0,%1,%2,%3}, {%4,%5,%6,%7}, {%8,%9}, {%0,%1,%2,%3};"
        : "+f"(c[0]), "+f"(c[1]), "+f"(c[2]), "+f"(c[3])
        : "r"(a[0]), "r"(a[1]), "r"(a[2]), "r"(a[3]), "r"(b[0]), "r"(b[1]));
}

__device__ __forceinline__ void cvt8(float4 f0, float4 f1, uint4& hi, uint4& lo) {
    float h0 = hf(f0.x), h1 = hf(f0.y), h2 = hf(f0.z), h3 = hf(f0.w);
    float h4 = hf(f1.x), h5 = hf(f1.y), h6 = hf(f1.z), h7 = hf(f1.w);
    hi.x = packh(h0, h1); hi.y = packh(h2, h3);
    hi.z = packh(h4, h5); hi.w = packh(h6, h7);
    lo.x = packh(f0.x - h0, f0.y - h1);
    lo.y = packh(f0.z - h2, f0.w - h3);
    lo.z = packh(f1.x - h4, f1.y - h5);
    lo.w = packh(f1.z - h6, f1.w - h7);
}

__device__ __forceinline__ void cpa16(uint32_t d, const void* s) {
    asm volatile("cp.async.cg.shared.global [%0], [%1], 16;" :: "r"(d), "l"(s));
}
__device__ __forceinline__ void cpcommit() {
    asm volatile("cp.async.commit_group;");
}
template <int N>
__device__ __forceinline__ void cpwait() {
    asm volatile("cp.async.wait_group %0;" :: "n"(N));
}

// ---------------------------------------------------------------------------
// Fused weight converter
// ---------------------------------------------------------------------------
#define WN0 4718592L
#define WN1 1572864L
#define WN2 4325376L
#define WTOT (WN0 + WN1 + 3 * WN2)

__global__ void wcvt_all_k(const float* __restrict__ cw, const float* __restrict__ pw,
                           const float* __restrict__ w1, const float* __restrict__ w3,
                           const float* __restrict__ w2,
                           __half* cwh, __half* cwl, __half* pwh, __half* pwl,
                           __half* w1h, __half* w1l, __half* w3h, __half* w3l,
                           __half* w2h, __half* w2l) {
    long i = (long)blockIdx.x * 256 + threadIdx.x;
    const float* src; __half* hi; __half* lo;
    if (i < WN0)              { src = cw; hi = cwh; lo = cwl; }
    else if ((i -= WN0) < WN1){ src = pw; hi = pwh; lo = pwl; }
    else if ((i -= WN1) < WN2){ src = w1; hi = w1h; lo = w1l; }
    else if ((i -= WN2) < WN2){ src = w3; hi = w3h; lo = w3l; }
    else { i -= WN2;            src = w2; hi = w2h; lo = w2l; }
    float4 f0 = ((const float4*)src)[i * 2];
    float4 f1 = ((const float4*)src)[i * 2 + 1];
    uint4 h, l;
    cvt8(f0, f1, h, l);
    ((uint4*)hi)[i] = h;
    ((uint4*)lo)[i] = l;
}

// ---------------------------------------------------------------------------
// GEMM mainloop — R11 structure. TERMS: 3 = hh+lh+hl; 2 = drop W-lo.
// ---------------------------------------------------------------------------
#define RSTRIDE 80
#define STAGE_BYTES 40960

struct LoaderPtrs {
    const __half *pa0, *pal0, *pa1, *pal1;
    const __half *pw0, *pwl0, *pw1, *pwl1;
};

template <int TERMS>
__device__ __forceinline__ void gemm_mainloop(
    uint32_t sb, char* sm, int tid, int K, const LoaderPtrs& P,
    const uint32_t* arow, const uint32_t* brow, float acc[4][4][4]) {
    const int r0l = tid >> 2, c0l = tid & 3;
    const int r1l = (tid + 256) >> 2;

    auto load_stage = [&](int s, int kc) {
        uint32_t base = sb + (uint32_t)s * STAGE_BYTES;
        {
            uint32_t d = base + (uint32_t)(r0l * RSTRIDE + c0l * 16);
            cpa16(d +     0, P.pa0  + kc);
            cpa16(d + 10240, P.pal0 + kc);
            cpa16(d + 20480, P.pw0  + kc);
            if (TERMS >= 3) cpa16(d + 30720, P.pwl0 + kc);
        }
        {
            uint32_t d = base + (uint32_t)(r1l * RSTRIDE + c0l * 16);
            cpa16(d +     0, P.pa1  + kc);
            cpa16(d + 10240, P.pal1 + kc);
            cpa16(d + 20480, P.pw1  + kc);
            if (TERMS >= 3) cpa16(d + 30720, P.pwl1 + kc);
        }
    };

    const int nc = K >> 5;
    load_stage(0, 0);
    cpcommit();

    for (int j = 0; j < nc; j++) {
        cpwait<0>();
        __syncthreads();
        if (j + 1 < nc) {
            load_stage((j + 1) & 1, (j + 1) << 5);
            cpcommit();
        }

        const uint32_t base = sb + (uint32_t)(j & 1) * STAGE_BYTES;
        #pragma unroll
        for (int ks = 0; ks < 2; ks++) {
            const uint32_t ko = (uint32_t)(ks * 32);
            uint32_t bh[4][2], bl[4][2];
            #pragma unroll
            for (int p = 0; p < 2; p++) {
                uint32_t t4[4];
                ldm_x4(t4, base + 20480 + brow[p] + ko);
                bh[2*p][0] = t4[0]; bh[2*p][1] = t4[1];
                bh[2*p+1][0] = t4[2]; bh[2*p+1][1] = t4[3];
                if (TERMS >= 3) {
                    ldm_x4(t4, base + 30720 + brow[p] + ko);
                    bl[2*p][0] = t4[0]; bl[2*p][1] = t4[1];
                    bl[2*p+1][0] = t4[2]; bl[2*p+1][1] = t4[3];
                }
            }
            uint32_t ahb[2][4], alb[2][4];
            ldm_x4(ahb[0], base +     0 + arow[0] + ko);
            ldm_x4(alb[0], base + 10240 + arow[0] + ko);
            #pragma unroll
            for (int mt = 0; mt < 4; mt++) {
                const int cur = mt & 1;
                if (mt < 3) {
                    ldm_x4(ahb[cur ^ 1], base +     0 + arow[mt + 1] + ko);
                    ldm_x4(alb[cur ^ 1], base + 10240 + arow[mt + 1] + ko);
                }
                #pragma unroll
                for (int nt = 0; nt < 4; nt++)
                    mma16816(acc[mt][nt], ahb[cur], bh[nt]);
                #pragma unroll
                for (int nt = 0; nt < 4; nt++)
                    mma16816(acc[mt][nt], alb[cur], bh[nt]);
                if (TERMS >= 3) {
                    #pragma unroll
                    for (int nt = 0; nt < 4; nt++)
                        mma16816(acc[mt][nt], ahb[cur], bl[nt]);
                }
            }
        }
    }
    __syncthreads();
}

#define GEMM_PROLOG                                                            \
    extern __shared__ __align__(16) char sm[];                                 \
    const uint32_t sb = smem_u32(sm);                                          \
    const int tid = threadIdx.x;                                               \
    const int warp = tid >> 5, lane = tid & 31;                                \
    const int wm = warp & 1, wn = warp >> 1;                                   \
    const int gid = lane >> 2, tg = lane & 3;                                  \
    const int l15 = lane & 15, l16 = (lane >> 4) & 1;                          \
    const int l7 = lane & 7, l8 = (lane >> 3) & 1;                             \
    uint32_t arow[4], brow[2];                                                 \
    _Pragma("unroll")                                                          \
    for (int mt = 0; mt < 4; mt++)                                             \
        arow[mt] = (uint32_t)((wm * 64 + mt * 16 + l15) * RSTRIDE + l16 * 16); \
    _Pragma("unroll")                                                          \
    for (int p = 0; p < 2; p++)                                                \
        brow[p] = (uint32_t)((wn * 32 + p * 16 + l7 + l16 * 8) * RSTRIDE + l8 * 16); \
    float acc[4][4][4];                                                        \
    _Pragma("unroll")                                                          \
    for (int i = 0; i < 4; i++)                                                \
        _Pragma("unroll")                                                      \
        for (int j = 0; j < 4; j++)                                            \
            _Pragma("unroll")                                                  \
            for (int c = 0; c < 4; c++) acc[i][j][c] = 0.f;                    \
    const int r0l = tid >> 2, c0l = tid & 3;                                   \
    const int r1l = (tid + 256) >> 2;

// ---------------------------------------------------------------------------
// Standard GEMM "NT" (proj / w2). Row base: by = blockIdx.y*byS + byO
// (byS=128,byO=0 normal; byS=T_,byO=T_-128 last-layer per-batch tiles).
// ---------------------------------------------------------------------------
template <int TERMS>
__global__ void __launch_bounds__(256, 2)
hgemm16(const __half* __restrict__ a_hi, const __half* __restrict__ a_lo,
        const __half* __restrict__ w_hi, const __half* __restrict__ w_lo,
        const float* __restrict__ bias, float* __restrict__ C,
        int M, int N, int K, int residual, int byS, int byO) {
    GEMM_PROLOG
    const int by = blockIdx.y * byS + byO, bx = blockIdx.x * 128;
    LoaderPtrs P;
    P.pa0  = a_hi + (size_t)(by + r0l) * K + c0l * 8;
    P.pal0 = a_lo + (size_t)(by + r0l) * K + c0l * 8;
    P.pa1  = a_hi + (size_t)(by + r1l) * K + c0l * 8;
    P.pal1 = a_lo + (size_t)(by + r1l) * K + c0l * 8;
    P.pw0  = w_hi + (size_t)(bx + r0l) * K + c0l * 8;
    P.pwl0 = w_lo + (size_t)(bx + r0l) * K + c0l * 8;
    P.pw1  = w_hi + (size_t)(bx + r1l) * K + c0l * 8;
    P.pwl1 = w_lo + (size_t)(bx + r1l) * K + c0l * 8;
    gemm_mainloop<TERMS>(sb, sm, tid, K, P, arow, brow, acc);

    const size_t mBase = (size_t)by + wm * 64;
    const int    nBase = bx + wn * 32;
    #pragma unroll
    for (int mt = 0; mt < 4; mt++) {
        #pragma unroll
        for (int nt = 0; nt < 4; nt++) {
            int c0 = nBase + nt * 8 + tg * 2;
            float b0 = bias ? bias[c0]     : 0.f;
            float b1 = bias ? bias[c0 + 1] : 0.f;
            size_t r0 = mBase + mt * 16 + gid;
            float* p0 = C + r0 * N + c0;
            float* p1 = C + (r0 + 8) * N + c0;
            float v00 = acc[mt][nt][0] + b0, v01 = acc[mt][nt][1] + b1;
            float v10 = acc[mt][nt][2] + b0, v11 = acc[mt][nt][3] + b1;
            if (residual) { v00 += p0[0]; v01 += p0[1]; v10 += p1[0]; v11 += p1[1]; }
            p0[0] = v00; p0[1] = v01;
            p1[0] = v10; p1[1] = v11;
        }
    }
}

// ---------------------------------------------------------------------------
// QKV GEMM with fused bias + RoPE + fp16 hi/lo split output. 3-term. Full M.
// ---------------------------------------------------------------------------
__global__ void __launch_bounds__(256, 2)
hgemm16_qkv(const __half* __restrict__ a_hi, const __half* __restrict__ a_lo,
            const __half* __restrict__ w_hi, const __half* __restrict__ w_lo,
            const float* __restrict__ bias,
            __half* __restrict__ qh, __half* __restrict__ ql,
            __half* __restrict__ kh, __half* __restrict__ kl,
            __half* __restrict__ vh, __half* __restrict__ vl) {
    GEMM_PROLOG
    const int K = D_;
    const int by = blockIdx.y * 128, bx = blockIdx.x * 128;
    LoaderPtrs P;
    P.pa0  = a_hi + (size_t)(by + r0l) * K + c0l * 8;
    P.pal0 = a_lo + (size_t)(by + r0l) * K + c0l * 8;
    P.pa1  = a_hi + (size_t)(by + r1l) * K + c0l * 8;
    P.pal1 = a_lo + (size_t)(by + r1l) * K + c0l * 8;
    P.pw0  = w_hi + (size_t)(bx + r0l) * K + c0l * 8;
    P.pwl0 = w_lo + (size_t)(bx + r0l) * K + c0l * 8;
    P.pw1  = w_hi + (size_t)(bx + r1l) * K + c0l * 8;
    P.pwl1 = w_lo + (size_t)(bx + r1l) * K + c0l * 8;
    gemm_mainloop<3>(sb, sm, tid, K, P, arow, brow, acc);

    float* smf = (float*)sm;
    #pragma unroll
    for (int mt = 0; mt < 4; mt++) {
        #pragma unroll
        for (int nt = 0; nt < 4; nt++) {
            int col = wn * 32 + nt * 8 + tg * 2;
            int row = wm * 64 + mt * 16 + gid;
            float b0 = bias[bx + col], b1 = bias[bx + col + 1];
            smf[row * 132 + col]           = acc[mt][nt][0] + b0;
            smf[row * 132 + col + 1]       = acc[mt][nt][1] + b1;
            smf[(row + 8) * 132 + col]     = acc[mt][nt][2] + b0;
            smf[(row + 8) * 132 + col + 1] = acc[mt][nt][3] + b1;
        }
    }
    __syncthreads();

    const int region = blockIdx.x >> 3;      // 0 q, 1 k, 2 v
    #pragma unroll 4
    for (int it = 0; it < 16; it++) {
        int idx = tid + it * 256;
        int r = idx >> 5;
        int c4 = (idx & 31) * 4;
        int mrow = by + r;
        float4 x4 = *(float4*)&smf[r * 132 + c4];
        float o0, o1, o2, o3;
        __half *dh, *dl;
        int dcol;
        if (region < 2) {
            int cg = bx + c4;
            int hc = cg & 63;
            int hi_half = hc & 32;
            float4 p4 = *(float4*)&smf[r * 132 + (hi_half ? c4 - 32 : c4 + 32)];
            int t = mrow & (T_ - 1);
            float oo[4];
            float xv[4] = {x4.x, x4.y, x4.z, x4.w};
            float pv[4] = {p4.x, p4.y, p4.z, p4.w};
            #pragma unroll
            for (int e = 0; e < 4; e++) {
                int i = (hc & 31) + e;
                float inv = exp2f((float)i * (-13.28771237954945f / 32.0f));
                float ang = (float)t * inv;
                float sn, cs;
                sincosf(ang, &sn, &cs);
                oo[e] = hi_half ? (xv[e] * cs + pv[e] * sn)
                                : (xv[e] * cs - pv[e] * sn);
            }
            if (region == 0) {
                o0 = oo[0] * 0.125f; o1 = oo[1] * 0.125f;
                o2 = oo[2] * 0.125f; o3 = oo[3] * 0.125f;
                dh = qh; dl = ql; dcol = cg;
            } else {
                o0 = oo[0]; o1 = oo[1]; o2 = oo[2]; o3 = oo[3];
                dh = kh; dl = kl; dcol = cg - D_;
            }
        } else {
            o0 = x4.x; o1 = x4.y; o2 = x4.z; o3 = x4.w;
            dh = vh; dl = vl; dcol = bx + c4 - 2 * D_;
        }
        float h0 = hf(o0), h1 = hf(o1), h2 = hf(o2), h3 = hf(o3);
        uint2 hh, ll;
        hh.x = packh(h0, h1); hh.y = packh(h2, h3);
        ll.x = packh(o0 - h0, o1 - h1); ll.y = packh(o2 - h2, o3 - h3);
        *(uint2*)(dh + (size_t)mrow * D_ + dcol) = hh;
        *(uint2*)(dl + (size_t)mrow * D_ + dcol) = ll;
    }
}

// ---------------------------------------------------------------------------
// Fused GLU GEMM — 2-term. Row base via byS/byO like hgemm16.
// ---------------------------------------------------------------------------
__global__ void __launch_bounds__(256, 2)
hgemm16_glu(const __half* __restrict__ a_hi, const __half* __restrict__ a_lo,
            const __half* __restrict__ w1h, const __half* __restrict__ w1l,
            const __half* __restrict__ w3h, const __half* __restrict__ w3l,
            __half* __restrict__ oh, __half* __restrict__ ol, int byS, int byO) {
    GEMM_PROLOG
    const int K = D_;
    const int by = blockIdx.y * byS + byO;
    const int bx64 = blockIdx.x * 64;
    LoaderPtrs P;
    P.pa0  = a_hi + (size_t)(by + r0l) * K + c0l * 8;
    P.pal0 = a_lo + (size_t)(by + r0l) * K + c0l * 8;
    P.pa1  = a_hi + (size_t)(by + r1l) * K + c0l * 8;
    P.pal1 = a_lo + (size_t)(by + r1l) * K + c0l * 8;
    P.pw0  = w1h + (size_t)(bx64 + r0l) * K + c0l * 8;
    P.pwl0 = w1l + (size_t)(bx64 + r0l) * K + c0l * 8;
    P.pw1  = w3h + (size_t)(bx64 + r0l) * K + c0l * 8;
    P.pwl1 = w3l + (size_t)(bx64 + r0l) * K + c0l * 8;
    gemm_mainloop<2>(sb, sm, tid, K, P, arow, brow, acc);

    float* smf = (float*)sm;
    #pragma unroll
    for (int mt = 0; mt < 4; mt++) {
        #pragma unroll
        for (int nt = 0; nt < 4; nt++) {
            int col = wn * 32 + nt * 8 + tg * 2;
            int row = wm * 64 + mt * 16 + gid;
            smf[row * 132 + col]           = acc[mt][nt][0];
            smf[row * 132 + col + 1]       = acc[mt][nt][1];
            smf[(row + 8) * 132 + col]     = acc[mt][nt][2];
            smf[(row + 8) * 132 + col + 1] = acc[mt][nt][3];
        }
    }
    __syncthreads();

    #pragma unroll 4
    for (int it = 0; it < 8; it++) {
        int idx = tid + it * 256;
        int r = idx >> 4;
        int c4 = (idx & 15) * 4;
        float4 uv = *(float4*)&smf[r * 132 + c4];
        float4 gv = *(float4*)&smf[r * 132 + c4 + 64];
        float o0 = uv.x / (1.f + expf(-uv.x)) * gv.x;
        float o1 = uv.y / (1.f + expf(-uv.y)) * gv.y;
        float o2 = uv.z / (1.f + expf(-uv.z)) * gv.z;
        float o3 = uv.w / (1.f + expf(-uv.w)) * gv.w;
        float h0 = hf(o0), h1 = hf(o1), h2 = hf(o2), h3 = hf(o3);
        uint2 hh, ll;
        hh.x = packh(h0, h1); hh.y = packh(h2, h3);
        ll.x = packh(o0 - h0, o1 - h1); ll.y = packh(o2 - h2, o3 - h3);
        size_t off = (size_t)(by + r) * HID_ + bx64 + c4;
        *(uint2*)(oh + off) = hh;
        *(uint2*)(ol + off) = ll;
    }
}

// ---------------------------------------------------------------------------
// Embedding gather
// ---------------------------------------------------------------------------
__global__ void embed_k(const int* __restrict__ tok, const float* __restrict__ wte,
                        float* __restrict__ x) {
    int m = blockIdx.x;
    int t = tok[m];
    const float4* src = (const float4*)(wte + (size_t)t * D_);
    float4* dst = (float4*)(x + (size_t)m * D_);
    dst[threadIdx.x] = src[threadIdx.x];
}

// ---------------------------------------------------------------------------
// LayerNorm cores
// ---------------------------------------------------------------------------
__device__ __forceinline__ void ln_core(const float* xr, int tid,
                                        float4& v, float& mean, float& rstd) {
    v = ((const float4*)xr)[tid];
    float s = v.x + v.y + v.z + v.w;
    float q = v.x*v.x + v.y*v.y + v.z*v.z + v.w*v.w;
    #pragma unroll
    for (int off = 16; off > 0; off >>= 1) {
        s += __shfl_down_sync(0xffffffffu, s, off);
        q += __shfl_down_sync(0xffffffffu, q, off);
    }
    __shared__ float ss[8], sq[8];
    int wi = tid >> 5, ln = tid & 31;
    if (ln == 0) { ss[wi] = s; sq[wi] = q; }
    __syncthreads();
    if (tid == 0) {
        float a = 0.f, c = 0.f;
        #pragma unroll
        for (int i = 0; i < 8; i++) { a += ss[i]; c += sq[i]; }
        ss[0] = a; sq[0] = c;
    }
    __syncthreads();
    mean = ss[0] * (1.f / D_);
    float var = sq[0] * (1.f / D_) - mean * mean;
    rstd = rsqrtf(var + 1e-5f);
}

__global__ void ln_k(const float* __restrict__ x, const float* __restrict__ w,
                     const float* __restrict__ b, float* __restrict__ o,
                     int rowStride) {
    int row = blockIdx.x, tid = threadIdx.x;
    float4 v; float mean, rstd;
    ln_core(x + (size_t)row * rowStride, tid, v, mean, rstd);
    float4 wv = ((const float4*)w)[tid];
    float4 bv = ((const float4*)b)[tid];
    float4 ov;
    ov.x = (v.x - mean) * rstd * wv.x + bv.x;
    ov.y = (v.y - mean) * rstd * wv.y + bv.y;
    ov.z = (v.z - mean) * rstd * wv.z + bv.z;
    ov.w = (v.w - mean) * rstd * wv.w + bv.w;
    ((float4*)(o + (size_t)row * D_))[tid] = ov;
}

// row = (blk/gs)*gstr + goff + (blk%gs). Normal: gs=M_, gstr=0, goff=0.
__global__ void ln_cvt_k(const float* __restrict__ x, const float* __restrict__ w,
                         const float* __restrict__ b, __half* __restrict__ hi,
                         __half* __restrict__ lo, int gs, int gstr, int goff) {
    int blk = blockIdx.x, tid = threadIdx.x;
    int row = (blk / gs) * gstr + goff + (blk % gs);
    float4 v; float mean, rstd;
    ln_core(x + (size_t)row * D_, tid, v, mean, rstd);
    float4 wv = ((const float4*)w)[tid];
    float4 bv = ((const float4*)b)[tid];
    float o0 = (v.x - mean) * rstd * wv.x + bv.x;
    float o1 = (v.y - mean) * rstd * wv.y + bv.y;
    float o2 = (v.z - mean) * rstd * wv.z + bv.z;
    float o3 = (v.w - mean) * rstd * wv.w + bv.w;
    size_t ob = (size_t)row * D_ + tid * 4;
    float h0 = hf(o0), h1 = hf(o1), h2 = hf(o2), h3 = hf(o3);
    uint2 hh, ll;
    hh.x = packh(h0, h1); hh.y = packh(h2, h3);
    ll.x = packh(o0 - h0, o1 - h1); ll.y = packh(o2 - h2, o3 - h3);
    *(uint2*)(hi + ob) = hh;
    *(uint2*)(lo + ob) = ll;
}

// ---------------------------------------------------------------------------
// MMA flash attention (proven R7 kernel) + q-tile offset for last layer.
// ---------------------------------------------------------------------------
#define ARS 72
#define ATT_SMEM 92160

__global__ void __launch_bounds__(128)
mma_attn(const __half* __restrict__ qh, const __half* __restrict__ ql,
         const __half* __restrict__ kh, const __half* __restrict__ kl,
         const __half* __restrict__ vh, const __half* __restrict__ vl,
         __half* __restrict__ oh, __half* __restrict__ ol, int q_off) {
    extern __shared__ __align__(16) __half sa[];
    const int qt = blockIdx.x + q_off, h = blockIdx.y, b = blockIdx.z;
    const int q0 = qt * 64;
    const int tid = threadIdx.x, w = tid >> 5, lane = tid & 31;
    const int gid = lane >> 2, tg = lane & 3;
    const int l7 = lane & 7, l8 = (lane >> 3) & 1, l16 = (lane >> 4) & 1;
    const uint32_t sb = smem_u32(sa);

    const int QHI = 0, QLO = 4608, STG = 9216, STGSZ = 18432;

    for (int i = tid; i < 1024; i += 128) {
        int arr = i >> 9, rem = i & 511, row = rem >> 3, ch = rem & 7;
        const __half* src = (arr ? ql : qh) +
            (size_t)(b * T_ + q0 + row) * D_ + h * 64 + ch * 8;
        *(uint4*)(sa + (arr ? QLO : QHI) + row * ARS + ch * 8) = *(const uint4*)src;
    }

    auto load_kv = [&](int s, int kt) {
        const __half* srcs[4] = {kh, kl, vh, vl};
        int base0 = STG + s * STGSZ;
        for (int i = tid; i < 2048; i += 128) {
            int arr = i >> 9, rem = i & 511, row = rem >> 3, ch = rem & 7;
            const __half* src = srcs[arr] +
                (size_t)(b * T_ + kt * 64 + row) * D_ + h * 64 + ch * 8;
            uint32_t dst = sb + (uint32_t)(base0 + arr * 4608 + row * ARS + ch * 8) * 2;
            cpa16(dst, src);
        }
    };

    load_kv(0, 0);
    cpcommit();
    __syncthreads();

    uint32_t aqh[4][4], aql[4][4];
    {
        uint32_t abase = sb + (uint32_t)((w * 16 + (lane & 15)) * ARS + l16 * 8) * 2;
        #pragma unroll
        for (int kc = 0; kc < 4; kc++) {
            ldm_x4(aqh[kc], abase + kc * 32);
            ldm_x4(aql[kc], abase + 9216 + kc * 32);
        }
    }

    float m0 = -1e30f, m1 = -1e30f, l0 = 0.f, l1 = 0.f;
    float O[8][4];
    #pragma unroll
    for (int n = 0; n < 8; n++)
        #pragma unroll
        for (int c = 0; c < 4; c++) O[n][c] = 0.f;

    const int nt = qt + 1;
    for (int kt = 0; kt < nt; kt++) {
        const int s = kt & 1;
        if (kt + 1 < nt) { load_kv(s ^ 1, kt + 1); cpcommit(); cpwait<1>(); }
        else             { cpwait<0>(); }
        __syncthreads();

        const uint32_t kbase = sb + (uint32_t)(STG + s * STGSZ) * 2;

        float S[8][4];
        #pragma unroll
        for (int n = 0; n < 8; n++)
            #pragma unroll
            for (int c = 0; c < 4; c++) S[n][c] = 0.f;

        #pragma unroll
        for (int kc = 0; kc < 4; kc++) {
            #pragma unroll
            for (int np = 0; np < 4; np++) {
                uint32_t addr = kbase +
                    (uint32_t)((np * 16 + l7 + l16 * 8) * ARS) * 2 + l8 * 16 + kc * 32;
                uint32_t bh4[4], bl4[4];
                ldm_x4(bh4, addr);
                ldm_x4(bl4, addr + 9216);
                mma16816(S[2*np],   aqh[kc], bh4 + 0);
                mma16816(S[2*np],   aql[kc], bh4 + 0);
                mma16816(S[2*np],   aqh[kc], bl4 + 0);
                mma16816(S[2*np+1], aqh[kc], bh4 + 2);
                mma16816(S[2*np+1], aql[kc], bh4 + 2);
                mma16816(S[2*np+1], aqh[kc], bl4 + 2);
            }
        }

        if (kt == qt) {
            #pragma unroll
            for (int n = 0; n < 8; n++)
                #pragma unroll
                for (int c = 0; c < 4; c++) {
                    int qg = w * 16 + gid + (c >> 1) * 8;
                    int kg = n * 8 + 2 * tg + (c & 1);
                    if (kg > qg) S[n][c] = -1e30f;
                }
        }

        float mt0 = -1e30f, mt1 = -1e30f;
        #pragma unroll
        for (int n = 0; n < 8; n++) {
            mt0 = fmaxf(mt0, fmaxf(S[n][0], S[n][1]));
            mt1 = fmaxf(mt1, fmaxf(S[n][2], S[n][3]));
        }
        mt0 = fmaxf(mt0, __shfl_xor_sync(0xffffffffu, mt0, 1));
        mt0 = fmaxf(mt0, __shfl_xor_sync(0xffffffffu, mt0, 2));
        mt1 = fmaxf(mt1, __shfl_xor_sync(0xffffffffu, mt1, 1));
        mt1 = fmaxf(mt1, __shfl_xor_sync(0xffffffffu, mt1, 2));
        float mn0 = fmaxf(m0, mt0), mn1 = fmaxf(m1, mt1);
        float a0 = expf(m0 - mn0), a1 = expf(m1 - mn1);
        float ps0 = 0.f, ps1 = 0.f;
        #pragma unroll
        for (int n = 0; n < 8; n++) {
            S[n][0] = expf(S[n][0] - mn0); ps0 += S[n][0];
            S[n][1] = expf(S[n][1] - mn0); ps0 += S[n][1];
            S[n][2] = expf(S[n][2] - mn1); ps1 += S[n][2];
            S[n][3] = expf(S[n][3] - mn1); ps1 += S[n][3];
        }
        ps0 += __shfl_xor_sync(0xffffffffu, ps0, 1);
        ps0 += __shfl_xor_sync(0xffffffffu, ps0, 2);
        ps1 += __shfl_xor_sync(0xffffffffu, ps1, 1);
        ps1 += __shfl_xor_sync(0xffffffffu, ps1, 2);
        l0 = l0 * a0 + ps0; l1 = l1 * a1 + ps1;
        m0 = mn0; m1 = mn1;
        #pragma unroll
        for (int n = 0; n < 8; n++) {
            O[n][0] *= a0; O[n][1] *= a0;
            O[n][2] *= a1; O[n][3] *= a1;
        }

        const uint32_t vbase = kbase + 18432;
        #pragma unroll
        for (int kc = 0; kc < 4; kc++) {
            float p0 = S[2*kc][0],   p1 = S[2*kc][1];
            float p2 = S[2*kc][2],   p3 = S[2*kc][3];
            float r0 = S[2*kc+1][0], r1 = S[2*kc+1][1];
            float r2 = S[2*kc+1][2], r3 = S[2*kc+1][3];
            float hp0 = hf(p0), hp1 = hf(p1), hp2 = hf(p2), hp3 = hf(p3);
            float hr0 = hf(r0), hr1 = hf(r1), hr2 = hf(r2), hr3 = hf(r3);
            uint32_t pah[4], pal[4];
            pah[0] = packh(hp0, hp1); pah[1] = packh(hp2, hp3);
            pah[2] = packh(hr0, hr1); pah[3] = packh(hr2, hr3);
            pal[0] = packh(p0 - hp0, p1 - hp1); pal[1] = packh(p2 - hp2, p3 - hp3);
            pal[2] = packh(r0 - hr0, r1 - hr1); pal[3] = packh(r2 - hr2, r3 - hr3);
            #pragma unroll
            for (int ndp = 0; ndp < 4; ndp++) {
                uint32_t addr = vbase +
                    (uint32_t)((kc * 16 + l7 + l8 * 8) * ARS) * 2 + ndp * 32 + l16 * 16;
                uint32_t bh4[4], bl4[4];
                ldm_x4_t(bh4, addr);
                ldm_x4_t(bl4, addr + 9216);
                mma16816(O[2*ndp],   pah, bh4 + 0);
                mma16816(O[2*ndp],   pal, bh4 + 0);
                mma16816(O[2*ndp],   pah, bl4 + 0);
                mma16816(O[2*ndp+1], pah, bh4 + 2);
                mma16816(O[2*ndp+1], pal, bh4 + 2);
                mma16816(O[2*ndp+1], pah, bl4 + 2);
            }
        }
        __syncthreads();
    }

    float i0 = 1.f / l0, i1 = 1.f / l1;
    size_t mrow0 = (size_t)(b * T_ + q0 + w * 16 + gid);
    #pragma unroll
    for (int nd = 0; nd < 8; nd++) {
        int col = h * 64 + nd * 8 + 2 * tg;
        float v0 = O[nd][0] * i0, v1 = O[nd][1] * i0;
        float v2 = O[nd][2] * i1, v3 = O[nd][3] * i1;
        float h0 = hf(v0), h1 = hf(v1), h2 = hf(v2), h3 = hf(v3);
        *(uint32_t*)(oh + mrow0 * D_ + col)       = packh(h0, h1);
        *(uint32_t*)(ol + mrow0 * D_ + col)       = packh(v0 - h0, v1 - h1);
        *(uint32_t*)(oh + (mrow0 + 8) * D_ + col) = packh(h2, h3);
        *(uint32_t*)(ol + (mrow0 + 8) * D_ + col) = packh(v2 - h2, v3 - h3);
    }
}

// ---------------------------------------------------------------------------
// Logits
// ---------------------------------------------------------------------------
__global__ void __launch_bounds__(256)
logits_k(const float* __restrict__ xf, const float* __restrict__ wte,
         float* __restrict__ out) {
    __shared__ float xs[B_ * D_];
    int tid = threadIdx.x;
    #pragma unroll
    for (int p = 0; p < 8; p++) {
        int i4 = tid + p * 256;
        float4 v = ((const float4*)xf)[i4];
        xs[i4 * 4 + 0] = v.x; xs[i4 * 4 + 1] = v.y;
        xs[i4 * 4 + 2] = v.z; xs[i4 * 4 + 3] = v.w;
    }
    __syncthreads();
    int n = blockIdx.x * 256 + tid;
    if (n >= V_) return;
    const float* wr = wte + (size_t)n * D_;
    float acc[8] = {0.f, 0.f, 0.f, 0.f, 0.f, 0.f, 0.f, 0.f};
    for (int k = 0; k < D_; k += 4) {
        float4 w = *(const float4*)(wr + k);
        #pragma unroll
        for (int b2 = 0; b2 < 8; b2++) {
            const float* xb = xs + b2 * D_ + k;
            acc[b2] += w.x * xb[0] + w.y * xb[1] + w.z * xb[2] + w.w * xb[3];
        }
    }
    #pragma unroll
    for (int b2 = 0; b2 < 8; b2++) out[(size_t)b2 * V_ + n] = acc[b2];
}

// ---------------------------------------------------------------------------
// Host orchestration
// ---------------------------------------------------------------------------
extern "C" void kernel_launch(void* const* d_in, const int* in_sizes, int n_in,
                              void* d_out, int out_size) {
    const int*   tokens   = (const int*)  d_in[0];
    const float* wte      = (const float*)d_in[1];
    const float* c_attn_w = (const float*)d_in[2];
    const float* c_attn_b = (const float*)d_in[3];
    const float* c_proj_w = (const float*)d_in[4];
    const float* c_proj_b = (const float*)d_in[5];
    const float* ln1_w    = (const float*)d_in[6];
    const float* ln1_b    = (const float*)d_in[7];
    const float* ln2_w    = (const float*)d_in[8];
    const float* ln2_b    = (const float*)d_in[9];
    const float* w1       = (const float*)d_in[10];
    const float* w3       = (const float*)d_in[11];
    const float* w2       = (const float*)d_in[12];
    const float* lnf_w    = (const float*)d_in[13];
    const float* lnf_b    = (const float*)d_in[14];
    float* out = (float*)d_out;

    float *x, *xf;
    cudaGetSymbolAddress((void**)&x,  g_x);
    cudaGetSymbolAddress((void**)&xf, g_xf);

    __half *ah, *al, *uh, *ul, *qh, *ql, *kh, *kl, *vh, *vl;
    cudaGetSymbolAddress((void**)&ah, g_ah);
    cudaGetSymbolAddress((void**)&al, g_al);
    cudaGetSymbolAddress((void**)&uh, g_uh);
    cudaGetSymbolAddress((void**)&ul, g_ul);
    cudaGetSymbolAddress((void**)&qh, g_qh);
    cudaGetSymbolAddress((void**)&ql, g_ql);
    cudaGetSymbolAddress((void**)&kh, g_kh);
    cudaGetSymbolAddress((void**)&kl, g_kl);
    cudaGetSymbolAddress((void**)&vh, g_vh);
    cudaGetSymbolAddress((void**)&vl, g_vl);

    __half *wch, *wcl, *wph, *wpl, *w1h, *w1l, *w3h, *w3l, *w2h, *w2l;
    cudaGetSymbolAddress((void**)&wch, g_wch);
    cudaGetSymbolAddress((void**)&wcl, g_wcl);
    cudaGetSymbolAddress((void**)&wph, g_wph);
    cudaGetSymbolAddress((void**)&wpl, g_wpl);
    cudaGetSymbolAddress((void**)&w1h, g_w1h);
    cudaGetSymbolAddress((void**)&w1l, g_w1l);
    cudaGetSymbolAddress((void**)&w3h, g_w3h);
    cudaGetSymbolAddress((void**)&w3l, g_w3l);
    cudaGetSymbolAddress((void**)&w2h, g_w2h);
    cudaGetSymbolAddress((void**)&w2l, g_w2l);

    const int SMEM = 2 * STAGE_BYTES;
    cudaFuncSetAttribute(hgemm16<3>, cudaFuncAttributeMaxDynamicSharedMemorySize, SMEM);
    cudaFuncSetAttribute(hgemm16<2>, cudaFuncAttributeMaxDynamicSharedMemorySize, SMEM);
    cudaFuncSetAttribute(hgemm16_qkv, cudaFuncAttributeMaxDynamicSharedMemorySize, SMEM);
    cudaFuncSetAttribute(hgemm16_glu, cudaFuncAttributeMaxDynamicSharedMemorySize, SMEM);
    cudaFuncSetAttribute(mma_attn, cudaFuncAttributeMaxDynamicSharedMemorySize, ATT_SMEM);

    wcvt_all_k<<<(int)(WTOT / 256), 256>>>(
        c_attn_w, c_proj_w, w1, w3, w2,
        wch, wcl, wph, wpl, w1h, w1l, w3h, w3l, w2h, w2l);

    embed_k<<<M_, 256>>>(tokens, wte, x);

    for (int l = 0; l < L_; l++) {
        const bool last = (l == L_ - 1);
        // ln1 + qkv always full M (K/V needed for all positions)
        ln_cvt_k<<<M_, 256>>>(x, ln1_w + l * D_, ln1_b + l * D_, ah, al,
                              M_, 0, 0);
        hgemm16_qkv<<<dim3(3 * D_ / 128, M_ / 128), 256, SMEM>>>(
            ah, al, wch + (size_t)l * 3 * D_ * D_, wcl + (size_t)l * 3 * D_ * D_,
            c_attn_b + l * 3 * D_, qh, ql, kh, kl, vh, vl);

        if (!last) {
            mma_attn<<<dim3(T_ / 64, NH_, B_), 128, ATT_SMEM>>>(
                qh, ql, kh, kl, vh, vl, ah, al, 0);
            hgemm16<2><<<dim3(D_ / 128, M_ / 128), 256, SMEM>>>(
                ah, al, wph + (size_t)l * D_ * D_, wpl + (size_t)l * D_ * D_,
                c_proj_b + l * D_, x, M_, D_, D_, 1, 128, 0);
            ln_cvt_k<<<M_, 256>>>(x, ln2_w + l * D_, ln2_b + l * D_, ah, al,
                                  M_, 0, 0);
            hgemm16_glu<<<dim3(HID_ / 64, M_ / 128), 256, SMEM>>>(
                ah, al, w1h + (size_t)l * HID_ * D_, w1l + (size_t)l * HID_ * D_,
                w3h + (size_t)l * HID_ * D_, w3l + (size_t)l * HID_ * D_,
                uh, ul, 128, 0);
            hgemm16<2><<<dim3(D_ / 128, M_ / 128), 256, SMEM>>>(
                uh, ul, w2h + (size_t)l * D_ * HID_, w2l + (size_t)l * D_ * HID_,
                nullptr, x, M_, D_, HID_, 1, 128, 0);
        } else {
            // Last layer: only rows b*T + [896, 1024) feed the output token.
            mma_attn<<<dim3(2, NH_, B_), 128, ATT_SMEM>>>(
                qh, ql, kh, kl, vh, vl, ah, al, T_ / 64 - 2);
            hgemm16<2><<<dim3(D_ / 128, B_), 256, SMEM>>>(
                ah, al, wph + (size_t)l * D_ * D_, wpl + (size_t)l * D_ * D_,
                c_proj_b + l * D_, x, M_, D_, D_, 1, T_, T_ - 128);
            ln_cvt_k<<<B_ * 128, 256>>>(x, ln2_w + l * D_, ln2_b + l * D_, ah, al,
                                        128, T_, T_ - 128);
            hgemm16_glu<<<dim3(HID_ / 64, B_), 256, SMEM>>>(
                ah, al, w1h + (size_t)l * HID_ * D_, w1l + (size_t)l * HID_ * D_,
                w3h + (size_t)l * HID_ * D_, w3l + (size_t)l * HID_ * D_,
                uh, ul, T_, T_ - 128);
            hgemm16<2><<<dim3(D_ / 128, B_), 256, SMEM>>>(
                uh, ul, w2h + (size_t)l * D_ * HID_, w2l + (size_t)l * D_ * HID_,
                nullptr, x, M_, D_, HID_, 1, T_, T_ - 128);
        }
    }

    ln_k<<<B_, 256>>>(x + (size_t)(T_ - 1) * D_, lnf_w, lnf_b, xf, T_ * D_);
    logits_k<<<(V_ + 255) / 256, 256>>>(xf, wte, out);
}